// round 8
// baseline (speedup 1.0000x reference)
#include <cuda_runtime.h>

// ---------------------------------------------------------------------------
// 6-qubit, 3-layer circuit, B=131072. EIGHT threads per state (thread bits
// t2,t1,t0 carry logical q0,q1,q2 through per-layer GF(2) relabelings), each
// thread holds 4 packed-f32x2 real + 4 imag regs (lane = q5; pack bit1 = q3,
// bit0 = q4). CNOT(0,1),(1,2) = zero-cost relabelings; CNOT(2,3) =
// thread-predicated SELs; CNOT(3,4) = free rename; CNOT(4,5)+(5,0) folded
// into the cross-thread q0-gate gather.
//
// Layer-by-layer mapping (rows = q0,q1,q2 as masks over lane bits t2t1t0):
//   L1: q0=100 q1=110 q2=111 ; partners: q0^6, q1^3, q2^1
//   L2: q0=100 q1=010 q2=101 ; partners: q0^5, q1^2, q2^1
//   L3: q0=100 q1=110 q2=011 ; partners: q0^7, q1^3, q2^1
// Final: Z0 sign=t2, Z2 sign=parity(ln&3), X1 partner = xor 3.
// ---------------------------------------------------------------------------

typedef unsigned long long u64;
#define SGN2 0x8000000080000000ULL

__device__ __forceinline__ u64 pk2(float a, float b) {
    u64 r; asm("mov.b64 %0,{%1,%2};" : "=l"(r) : "f"(a), "f"(b)); return r;
}
__device__ __forceinline__ void upk2(u64 v, float& a, float& b) {
    asm("mov.b64 {%0,%1},%2;" : "=f"(a), "=f"(b) : "l"(v));
}
__device__ __forceinline__ u64 bc2(float a) { return pk2(a, a); }
__device__ __forceinline__ u64 f2mul(u64 a, u64 b) {
    u64 d; asm("mul.rn.f32x2 %0,%1,%2;" : "=l"(d) : "l"(a), "l"(b)); return d;
}
__device__ __forceinline__ u64 f2fma(u64 a, u64 b, u64 c) {
    u64 d; asm("fma.rn.f32x2 %0,%1,%2,%3;" : "=l"(d) : "l"(a), "l"(b), "l"(c)); return d;
}
__device__ __forceinline__ u64 f2add(u64 a, u64 b) {
    u64 d; asm("add.rn.f32x2 %0,%1,%2;" : "=l"(d) : "l"(a), "l"(b)); return d;
}
__device__ __forceinline__ u64 f2swap(u64 a) {
    u64 d;
    asm("{\n\t.reg .b32 x,y;\n\tmov.b64 {x,y},%1;\n\tmov.b64 %0,{y,x};\n\t}"
        : "=l"(d) : "l"(a));
    return d;
}

// Fused per-(l,q) SU(2) unitary U = Rz*Ry*Rx. 48 u64 slots per layer:
//  q0 : [0..4]   ar, ai, br, bi, -bi
//  q1 : [6..9]   ar, ai, br, bi
//  q2 : [10..13] ar, ai, br, bi
//  q3 : [16..22] ar, ai, -ai, br, -br, bi, -bi
//  q4 : [24..30] same 7-slot layout
//  q5 : [32..37] (ar,ar),(-ai,ai),(br,-br),(-bi,-bi),(ai,-ai),(bi,bi)
__device__ u64 g_u[3 * 48];

__global__ void prep_kernel(const float* __restrict__ theta) {
    int t = threadIdx.x;
    if (t < 18) {
        int l = t / 6, q = t % 6;
        const float* th = theta + t * 3;
        float sx, cx, sy, cy, sz, cz;
        __sincosf(th[0] * 0.5f, &sx, &cx);
        __sincosf(th[1] * 0.5f, &sy, &cy);
        float z = th[2] * 0.5f;
        // Last-applied RZ on Z-measured (even) qubits, last layer: unobservable.
        if (l == 2 && (q % 2 == 0)) z = 0.0f;
        __sincosf(z, &sz, &cz);
        float m00r =  cy * cx, m00i =  sy * sx;
        float m01r = -sy * cx, m01i = -cy * sx;
        float ar = cz * m00r + sz * m00i, ai = cz * m00i - sz * m00r;
        float br = cz * m01r + sz * m01i, bi = cz * m01i - sz * m01r;
        u64* g = g_u + l * 48;
        if (q == 0) {
            g[0] = bc2(ar); g[1] = bc2(ai); g[2] = bc2(br);
            g[3] = bc2(bi); g[4] = bc2(-bi);
        } else if (q == 1) {
            g[6] = bc2(ar); g[7] = bc2(ai); g[8] = bc2(br); g[9] = bc2(bi);
        } else if (q == 2) {
            g[10] = bc2(ar); g[11] = bc2(ai); g[12] = bc2(br); g[13] = bc2(bi);
        } else if (q < 5) {
            u64* h = g + 16 + (q - 3) * 8;
            h[0] = bc2(ar); h[1] = bc2(ai); h[2] = bc2(-ai);
            h[3] = bc2(br); h[4] = bc2(-br); h[5] = bc2(bi); h[6] = bc2(-bi);
        } else {
            u64* h = g + 32;
            h[0] = pk2(ar, ar);   h[1] = pk2(-ai, ai);
            h[2] = pk2(br, -br);  h[3] = pk2(-bi, -bi);
            h[4] = pk2(ai, -ai);  h[5] = pk2(bi, bi);
        }
    }
}

// Local SU(2) on pack bit (MP=2 -> q3, MP=1 -> q4), 4 packs = 2 butterflies.
template <int MP>
__device__ __forceinline__ void su2_loc(u64* R, u64* I, const u64* __restrict__ u) {
    u64 ar = u[0], ai = u[1], nai = u[2];
    u64 br = u[3], nbr = u[4], bi = u[5], nbi = u[6];
#pragma unroll
    for (int g = 0; g < 2; g++) {
        int p0 = (g & (MP - 1)) | ((g & ~(MP - 1)) << 1);
        int p1 = p0 | MP;
        u64 Ar = R[p0], Ai = I[p0], Br = R[p1], Bi = I[p1];
        R[p0] = f2fma(nbi, Bi, f2fma(br, Br, f2fma(nai, Ai, f2mul(ar, Ar))));
        I[p0] = f2fma(br, Bi, f2fma(bi, Br, f2fma(ai, Ar, f2mul(ar, Ai))));
        R[p1] = f2fma(ai, Bi, f2fma(ar, Br, f2fma(nbi, Ai, f2mul(nbr, Ar))));
        I[p1] = f2fma(nai, Br, f2fma(ar, Bi, f2fma(bi, Ar, f2mul(nbr, Ai))));
    }
}

// Local SU(2) on qubit 5 (lane), within-pack butterfly via half-swap.
__device__ __forceinline__ void su2_q5(u64* R, u64* I, const u64* __restrict__ u) {
    u64 aa = u[0], am = u[1], bp = u[2], nb2 = u[3], ap = u[4], bb = u[5];
#pragma unroll
    for (int p = 0; p < 4; p++) {
        u64 r = R[p], m = I[p];
        u64 sr = f2swap(r), sm = f2swap(m);
        R[p] = f2fma(nb2, sm, f2fma(bp, sr, f2fma(am, m, f2mul(aa, r))));
        I[p] = f2fma(bb, sr, f2fma(bp, sm, f2fma(ap, r, f2mul(aa, m))));
    }
}

// Pure cross-thread SU(2) gate (q1/q2): partner = lane xor PX, role r:
//   r=0: new = a*L + b*M ;  r=1: new = a**L - b**M
template <int PX>
__device__ __forceinline__ void cross_gate(u64* R, u64* I,
                                           const u64* __restrict__ cf, int role) {
    u64 m1   = role ? SGN2 : 0ULL;
    u64 ar   = cf[0];
    u64 cai  = cf[1] ^ m1;
    u64 ncai = cai ^ SGN2;
    u64 cbr  = cf[2] ^ m1;
    u64 bi   = cf[3];
    u64 nbi  = bi ^ SGN2;
#pragma unroll
    for (int p = 0; p < 4; p++) {
        u64 LR = R[p], LI = I[p];
        u64 MR = __shfl_xor_sync(0xffffffffu, LR, PX);
        u64 MI = __shfl_xor_sync(0xffffffffu, LI, PX);
        R[p] = f2fma(nbi, MI, f2fma(cbr, MR, f2fma(ncai, LI, f2mul(ar, LR))));
        I[p] = f2fma(bi, MR, f2fma(cbr, MI, f2fma(cai, LR, f2mul(ar, LI))));
    }
}

// Cross-thread q0 gate with CNOT(4,5) + CNOT(5,0) folded into the gather.
// Partner = lane xor PX0 (flips logical q0 only); role/sign by t2.
template <int PX0>
__device__ __forceinline__ void q0_gate(u64* R, u64* I,
                                        const u64* __restrict__ cf, int t2) {
    u64 smask = t2 ? SGN2 : 0ULL;
    u64 car  = cf[0];
    u64 cai  = cf[1] ^ smask;
    u64 ncai = cai ^ SGN2;
    u64 cbr  = cf[2] ^ smask;
    u64 cbi  = cf[3];
    u64 ncbi = cf[4];
#pragma unroll
    for (int p = 0; p < 4; p++) {
        u64 LR = R[p], LI = I[p];
        u64 MR = __shfl_xor_sync(0xffffffffu, LR, PX0);
        u64 MI = __shfl_xor_sync(0xffffffffu, LI, PX0);
        float lr0, lr1, li0, li1, mr0, mr1, mi0, mi1;
        upk2(LR, lr0, lr1); upk2(LI, li0, li1);
        upk2(MR, mr0, mr1); upk2(MI, mi0, mi1);
        u64 AR, AI, BR, BI;
        if ((p & 1) == 0) {  // q4=0: C45 identity, C50 hi-lane cross
            AR = pk2(lr0, mr1); AI = pk2(li0, mi1);
            BR = pk2(mr0, lr1); BI = pk2(mi0, li1);
        } else {             // q4=1: C45 lane-swap then C50
            AR = pk2(lr1, mr0); AI = pk2(li1, mi0);
            BR = pk2(mr1, lr0); BI = pk2(mi1, li0);
        }
        R[p] = f2fma(ncbi, BI, f2fma(cbr, BR, f2fma(ncai, AI, f2mul(car, AR))));
        I[p] = f2fma(cbi, BR, f2fma(cbr, BI, f2fma(cai, AR, f2mul(car, AI))));
    }
}

// One layer. PX0/PX1 = partner xors for q0/q1 gates; M1/M2 = lane-bit masks
// whose parity gives the logical q1/q2 value at this thread (post-relabel).
template <int PX0, int PX1, int M1, int M2>
__device__ __forceinline__ void layer(u64* R, u64* I,
                                      const u64* __restrict__ cf, int ln) {
    bool c = (__popc(ln & M2) & 1) != 0;  // q2 value -> CNOT(2,3) + q2-gate role
    // CNOT(2,3): threads with q2=1 flip pack bit1 (swap packs 0<->2, 1<->3)
#pragma unroll
    for (int p = 0; p < 2; p++) {
        u64 a = R[p], b = R[p + 2];
        R[p] = c ? b : a;  R[p + 2] = c ? a : b;
        a = I[p]; b = I[p + 2];
        I[p] = c ? b : a;  I[p + 2] = c ? a : b;
    }
    // CNOT(3,4): packs with bit1=1 flip bit0 (free rename)
    { u64 tt = R[2]; R[2] = R[3]; R[3] = tt; tt = I[2]; I[2] = I[3]; I[3] = tt; }

    q0_gate<PX0>(R, I, cf, (ln >> 2) & 1);
    cross_gate<PX1>(R, I, cf + 6, __popc(ln & M1) & 1);
    cross_gate<1>(R, I, cf + 10, (int)c);
    su2_loc<2>(R, I, cf + 16);  // q3 (pack bit1)
    su2_loc<1>(R, I, cf + 24);  // q4 (pack bit0)
    su2_q5(R, I, cf + 32);      // q5 (lane)
}

__global__ __launch_bounds__(128, 6) void qsim_kernel(
    const float* __restrict__ x, float* __restrict__ out, int Bn)
{
    int gid = blockIdx.x * 128 + threadIdx.x;
    int st = gid >> 3;
    if (st >= Bn) return;
    int ln = threadIdx.x & 31;
    int t0 = ln & 1, t1 = (ln >> 1) & 1, t2 = (ln >> 2) & 1;

    // --- encoding: per-qubit 2-vector after RX(a) RZ(a/2) on |0> ---
    const float4* x4 = reinterpret_cast<const float4*>(x) + (long)st * 6;
    float u0r[6], u0i[6], u1r[6], u1i[6];
#pragma unroll
    for (int q = 0; q < 6; q++) {
        float4 v = __ldg(&x4[q]);
        float a = (v.x + v.y + v.z + v.w) * 0.25f;
        a = fminf(6.0f, fmaxf(-6.0f, a)) * (3.14159265358979323846f / 6.0f);
        float s2, c2, s4, c4;
        __sincosf(a * 0.5f, &s2, &c2);
        __sincosf(a * 0.25f, &s4, &c4);
        u0r[q] = c2 * c4;  u0i[q] = -c2 * s4;
        u1r[q] = s2 * s4;  u1i[q] = -s2 * c4;
    }

    // --- product state. Initial mapping: q0=t2, q1=t1, q2=t0;
    //     lane = q5; pack bit0 = q4, bit1 = q3. ---
    float a0r = t2 ? u1r[0] : u0r[0],  a0i = t2 ? u1i[0] : u0i[0];
    float a1r = t1 ? u1r[1] : u0r[1],  a1i = t1 ? u1i[1] : u0i[1];
    float a2r = t0 ? u1r[2] : u0r[2],  a2i = t0 ? u1i[2] : u0i[2];
    float pr01 = a0r * a1r - a0i * a1i;
    float pi01 = a0r * a1i + a0i * a1r;
    float cr = pr01 * a2r - pi01 * a2i;
    float ci = pr01 * a2i + pi01 * a2r;

    u64 R[4], I[4];
    R[0] = pk2(cr * u0r[5] - ci * u0i[5], cr * u1r[5] - ci * u1i[5]);
    I[0] = pk2(cr * u0i[5] + ci * u0r[5], cr * u1i[5] + ci * u1r[5]);
    {   // expand q4 (pack bit0)
        u64 a0 = bc2(u0r[4]), b0 = bc2(u0i[4]), nb0 = bc2(-u0i[4]);
        u64 a1 = bc2(u1r[4]), b1 = bc2(u1i[4]), nb1 = bc2(-u1i[4]);
        u64 tr = R[0], ti = I[0];
        R[1] = f2fma(nb1, ti, f2mul(a1, tr));
        I[1] = f2fma(b1, tr, f2mul(a1, ti));
        R[0] = f2fma(nb0, ti, f2mul(a0, tr));
        I[0] = f2fma(b0, tr, f2mul(a0, ti));
    }
    {   // expand q3 (pack bit1)
        u64 a0 = bc2(u0r[3]), b0 = bc2(u0i[3]), nb0 = bc2(-u0i[3]);
        u64 a1 = bc2(u1r[3]), b1 = bc2(u1i[3]), nb1 = bc2(-u1i[3]);
#pragma unroll
        for (int j = 0; j < 2; j++) {
            u64 tr = R[j], ti = I[j];
            R[j + 2] = f2fma(nb1, ti, f2mul(a1, tr));
            I[j + 2] = f2fma(b1, tr, f2mul(a1, ti));
            R[j]     = f2fma(nb0, ti, f2mul(a0, tr));
            I[j]     = f2fma(b0, tr, f2mul(a0, ti));
        }
    }

    // --- 3 layers (partner xors / role masks per the GF(2) tracking) ---
    layer<6, 3, 6, 7>(R, I, g_u + 0,  ln);
    layer<5, 2, 2, 5>(R, I, g_u + 48, ln);
    layer<7, 3, 6, 3>(R, I, g_u + 96, ln);

    // --- measurements. Final mapping: q0=t2, q1=t2^t1, q2=t1^t0. ---
    u64 aS = 0, az4 = 0, ax1 = 0, ax3 = 0, ax5 = 0;
#pragma unroll
    for (int p = 0; p < 4; p++) {
        u64 pr = f2fma(I[p], I[p], f2mul(R[p], R[p]));
        aS  = f2add(aS, pr);
        az4 = f2add(az4, (p & 1) ? (pr ^ SGN2) : pr);
        if (!(p & 2)) ax3 = f2fma(R[p], R[p | 2], f2fma(I[p], I[p | 2], ax3));
        ax5 = f2fma(R[p], f2swap(R[p]), f2fma(I[p], f2swap(I[p]), ax5));
        u64 PR = __shfl_xor_sync(0xffffffffu, R[p], 3);
        u64 PI = __shfl_xor_sync(0xffffffffu, I[p], 3);
        ax1 = f2fma(R[p], PR, f2fma(I[p], PI, ax1));
    }
    float lo, hi;
    upk2(aS, lo, hi);  float S0 = lo + hi;
    float z0 = t2 ? -S0 : S0;                       // Z on q0 = t2
    float z2 = ((t1 ^ t0) != 0) ? -S0 : S0;         // Z on q2 = t1^t0
    upk2(az4, lo, hi); float z4 = lo + hi;
    upk2(ax1, lo, hi); float x1 = lo + hi;          // full two-sided sum
    upk2(ax3, lo, hi); float x3 = lo + hi;
    upk2(ax5, lo, hi); float x5 = lo;               // both lanes same sum

    // reduce across the 8-thread group
#pragma unroll
    for (int d = 1; d < 8; d <<= 1) {
        z0 += __shfl_xor_sync(0xffffffffu, z0, d);
        z2 += __shfl_xor_sync(0xffffffffu, z2, d);
        z4 += __shfl_xor_sync(0xffffffffu, z4, d);
        x1 += __shfl_xor_sync(0xffffffffu, x1, d);
        x3 += __shfl_xor_sync(0xffffffffu, x3, d);
        x5 += __shfl_xor_sync(0xffffffffu, x5, d);
    }
    x3 *= 2.0f; x5 *= 2.0f;

    if ((ln & 7) == 0) {
        float4* o4 = reinterpret_cast<float4*>(out) + (long)st * 2;
        o4[0] = make_float4(z0, x1, z2, x3);
        o4[1] = make_float4(z4, x5, z0, x1);
    }
}

extern "C" void kernel_launch(void* const* d_in, const int* in_sizes, int n_in,
                              void* d_out, int out_size) {
    const float* x     = (const float*)d_in[0];
    const float* theta = (const float*)d_in[1];
    float* out = (float*)d_out;
    int Bn = in_sizes[0] / 24;

    prep_kernel<<<1, 32>>>(theta);
    long threads = 8L * Bn;
    int blocks = (int)((threads + 127) / 128);
    qsim_kernel<<<blocks, 128>>>(x, out, Bn);
}

// round 9
// speedup vs baseline: 1.8490x; 1.8490x over previous
#include <cuda_runtime.h>

// ---------------------------------------------------------------------------
// 6-qubit, 3-layer circuit, B=131072. FOUR threads per state (t1=q0, t0=q1),
// each holding 8 packed-f32x2 real + 8 imag regs (lane = q5; pack bits
// 2..0 = q2,q3,q4). CNOT(0,1) handled as a zero-cost thread-bit relabeling
// that alternates per layer (template<int S>); CNOT(4,5)+(5,0) folded into
// the cross-thread q0 gate gather; CNOT(1,2) = thread-predicated SELs;
// CNOT(2,3),(3,4) = free register renames.
// Round 9: force 6 CTAs/SM (85 regs) + halve MUFU count via double-angle.
// ---------------------------------------------------------------------------

typedef unsigned long long u64;
#define SGN2 0x8000000080000000ULL

__device__ __forceinline__ u64 pk2(float a, float b) {
    u64 r; asm("mov.b64 %0,{%1,%2};" : "=l"(r) : "f"(a), "f"(b)); return r;
}
__device__ __forceinline__ void upk2(u64 v, float& a, float& b) {
    asm("mov.b64 {%0,%1},%2;" : "=f"(a), "=f"(b) : "l"(v));
}
__device__ __forceinline__ u64 bc2(float a) { return pk2(a, a); }
__device__ __forceinline__ u64 f2mul(u64 a, u64 b) {
    u64 d; asm("mul.rn.f32x2 %0,%1,%2;" : "=l"(d) : "l"(a), "l"(b)); return d;
}
__device__ __forceinline__ u64 f2fma(u64 a, u64 b, u64 c) {
    u64 d; asm("fma.rn.f32x2 %0,%1,%2,%3;" : "=l"(d) : "l"(a), "l"(b), "l"(c)); return d;
}
__device__ __forceinline__ u64 f2add(u64 a, u64 b) {
    u64 d; asm("add.rn.f32x2 %0,%1,%2;" : "=l"(d) : "l"(a), "l"(b)); return d;
}
__device__ __forceinline__ u64 f2swap(u64 a) {
    u64 d;
    asm("{\n\t.reg .b32 x,y;\n\tmov.b64 {x,y},%1;\n\tmov.b64 %0,{y,x};\n\t}"
        : "=l"(d) : "l"(a));
    return d;
}

// Fused per-(l,q) SU(2) unitary U = Rz*Ry*Rx.  48 u64 slots per layer:
//  q0 : [0..4]   ar, ai, br, bi, -bi          (broadcast pairs)
//  q1 : [8..11]  ar, ai, br, bi               (broadcast pairs)
//  q2 : [16..22] ar, ai, -ai, br, -br, bi, -bi
//  q3 : [24..30] same
//  q4 : [32..38] same
//  q5 : [40..45] (ar,ar),(-ai,ai),(br,-br),(-bi,-bi),(ai,-ai),(bi,bi)
__device__ u64 g_u[3 * 48];

__global__ void prep_kernel(const float* __restrict__ theta) {
    int t = threadIdx.x;
    if (t < 18) {
        int l = t / 6, q = t % 6;
        const float* th = theta + t * 3;
        float sx, cx, sy, cy, sz, cz;
        __sincosf(th[0] * 0.5f, &sx, &cx);
        __sincosf(th[1] * 0.5f, &sy, &cy);
        float z = th[2] * 0.5f;
        // Last-applied RZ on Z-measured (even) qubits, last layer: unobservable.
        if (l == 2 && (q % 2 == 0)) z = 0.0f;
        __sincosf(z, &sz, &cz);
        float m00r =  cy * cx, m00i =  sy * sx;
        float m01r = -sy * cx, m01i = -cy * sx;
        float ar = cz * m00r + sz * m00i, ai = cz * m00i - sz * m00r;
        float br = cz * m01r + sz * m01i, bi = cz * m01i - sz * m01r;
        u64* g = g_u + l * 48;
        if (q == 0) {
            g[0] = bc2(ar); g[1] = bc2(ai); g[2] = bc2(br);
            g[3] = bc2(bi); g[4] = bc2(-bi);
        } else if (q == 1) {
            g[8] = bc2(ar); g[9] = bc2(ai); g[10] = bc2(br); g[11] = bc2(bi);
        } else if (q < 5) {
            u64* h = g + 16 + (q - 2) * 8;
            h[0] = bc2(ar); h[1] = bc2(ai); h[2] = bc2(-ai);
            h[3] = bc2(br); h[4] = bc2(-br); h[5] = bc2(bi); h[6] = bc2(-bi);
        } else {
            u64* h = g + 40;
            h[0] = pk2(ar, ar);   h[1] = pk2(-ai, ai);
            h[2] = pk2(br, -br);  h[3] = pk2(-bi, -bi);
            h[4] = pk2(ai, -ai);  h[5] = pk2(bi, bi);
        }
    }
}

// Local SU(2) on a pack bit (MP = 4 -> q2, 2 -> q3, 1 -> q4).
template <int MP>
__device__ __forceinline__ void su2_loc(u64* R, u64* I, const u64* __restrict__ u) {
    u64 ar = u[0], ai = u[1], nai = u[2];
    u64 br = u[3], nbr = u[4], bi = u[5], nbi = u[6];
#pragma unroll
    for (int g = 0; g < 4; g++) {
        int p0 = (g & (MP - 1)) | ((g & ~(MP - 1)) << 1);
        int p1 = p0 | MP;
        u64 Ar = R[p0], Ai = I[p0], Br = R[p1], Bi = I[p1];
        R[p0] = f2fma(nbi, Bi, f2fma(br, Br, f2fma(nai, Ai, f2mul(ar, Ar))));
        I[p0] = f2fma(br, Bi, f2fma(bi, Br, f2fma(ai, Ar, f2mul(ar, Ai))));
        R[p1] = f2fma(ai, Bi, f2fma(ar, Br, f2fma(nbi, Ai, f2mul(nbr, Ar))));
        I[p1] = f2fma(nai, Br, f2fma(ar, Bi, f2fma(bi, Ar, f2mul(nbr, Ai))));
    }
}

// Local SU(2) on qubit 5 (lane), within-pack butterfly via half-swap.
__device__ __forceinline__ void su2_q5(u64* R, u64* I, const u64* __restrict__ u) {
    u64 aa = u[0], am = u[1], bp = u[2], nb2 = u[3], ap = u[4], bb = u[5];
#pragma unroll
    for (int p = 0; p < 8; p++) {
        u64 r = R[p], m = I[p];
        u64 sr = f2swap(r), sm = f2swap(m);
        R[p] = f2fma(nb2, sm, f2fma(bp, sr, f2fma(am, m, f2mul(aa, r))));
        I[p] = f2fma(bb, sr, f2fma(bp, sm, f2fma(ap, r, f2mul(aa, m))));
    }
}

__device__ __forceinline__ void swp(u64* A, int i, int j) {
    u64 t = A[i]; A[i] = A[j]; A[j] = t;
}

// One layer. S = thread-bit mapping AFTER this layer's CNOT(0,1) relabel:
//   S=1: q0=t1, q1=t0^t1 ; S=0: q0=t1, q1=t0.
template <int S>
__device__ __forceinline__ void layer(u64* R, u64* I, const u64* __restrict__ cf,
                                      int t0, int t1) {
    int q1log = S ? (t0 ^ t1) : t0;
    // CNOT(1,2): threads with q1log==1 flip pack bit2.
    bool c = (q1log != 0);
#pragma unroll
    for (int p = 0; p < 4; p++) {
        u64 a = R[p], b = R[p + 4];
        R[p] = c ? b : a;  R[p + 4] = c ? a : b;
        a = I[p]; b = I[p + 4];
        I[p] = c ? b : a;  I[p + 4] = c ? a : b;
    }
    // CNOT(2,3): packs with bit2=1 flip bit1 (free renames)
    swp(R, 4, 6); swp(R, 5, 7); swp(I, 4, 6); swp(I, 5, 7);
    // CNOT(3,4): packs with bit1=1 flip bit0
    swp(R, 2, 3); swp(R, 6, 7); swp(I, 2, 3); swp(I, 6, 7);

    // q0 gate (cross-thread), CNOT(4,5) + CNOT(5,0) folded into the gather.
    // Partner flips logical q0 keeping q1log: xor 3 (S=1) / xor 2 (S=0).
    {
        u64 smask = t1 ? SGN2 : 0ULL;
        u64 car  = cf[0];
        u64 cai  = cf[1] ^ smask;
        u64 ncai = cai ^ SGN2;
        u64 cbr  = cf[2] ^ smask;
        u64 cbi  = cf[3];
        u64 ncbi = cf[4];
        constexpr int PX = S ? 3 : 2;
#pragma unroll
        for (int p = 0; p < 8; p++) {
            u64 LR = R[p], LI = I[p];
            u64 MR = __shfl_xor_sync(0xffffffffu, LR, PX);
            u64 MI = __shfl_xor_sync(0xffffffffu, LI, PX);
            float lr0, lr1, li0, li1, mr0, mr1, mi0, mi1;
            upk2(LR, lr0, lr1); upk2(LI, li0, li1);
            upk2(MR, mr0, mr1); upk2(MI, mi0, mi1);
            u64 AR, AI, BR, BI;
            if ((p & 1) == 0) {  // q4=0: C45 identity, C50 hi-lane cross
                AR = pk2(lr0, mr1); AI = pk2(li0, mi1);
                BR = pk2(mr0, lr1); BI = pk2(mi0, li1);
            } else {             // q4=1: C45 lane-swap then C50
                AR = pk2(lr1, mr0); AI = pk2(li1, mi0);
                BR = pk2(mr1, lr0); BI = pk2(mi1, li0);
            }
            R[p] = f2fma(ncbi, BI, f2fma(cbr, BR, f2fma(ncai, AI, f2mul(car, AR))));
            I[p] = f2fma(cbi, BR, f2fma(cbr, BI, f2fma(cai, AR, f2mul(car, AI))));
        }
    }

    // q1 gate (cross-thread, partner xor 1, role = q1log):
    //   r=0: new = a*L + b*M ;  r=1: new = a**L - b**M
    {
        u64 m1   = q1log ? SGN2 : 0ULL;
        u64 ar   = cf[8];
        u64 cai  = cf[9] ^ m1;
        u64 ncai = cai ^ SGN2;
        u64 cbr  = cf[10] ^ m1;
        u64 bi   = cf[11];
        u64 nbi  = bi ^ SGN2;
#pragma unroll
        for (int p = 0; p < 8; p++) {
            u64 LR = R[p], LI = I[p];
            u64 MR = __shfl_xor_sync(0xffffffffu, LR, 1);
            u64 MI = __shfl_xor_sync(0xffffffffu, LI, 1);
            R[p] = f2fma(nbi, MI, f2fma(cbr, MR, f2fma(ncai, LI, f2mul(ar, LR))));
            I[p] = f2fma(bi, MR, f2fma(cbr, MI, f2fma(cai, LR, f2mul(ar, LI))));
        }
    }

    su2_loc<4>(R, I, cf + 16);  // q2 (pack bit2)
    su2_loc<2>(R, I, cf + 24);  // q3 (pack bit1)
    su2_loc<1>(R, I, cf + 32);  // q4 (pack bit0)
    su2_q5(R, I, cf + 40);      // q5 (lane)
}

__global__ __launch_bounds__(128, 6) void qsim_kernel(
    const float* __restrict__ x, float* __restrict__ out, int Bn)
{
    int gid = blockIdx.x * 128 + threadIdx.x;
    int st = gid >> 2;
    if (st >= Bn) return;
    int t = gid & 3;
    int t0 = t & 1, t1 = (t >> 1) & 1;

    // --- encoding: per-qubit 2-vector after RX(a) RZ(a/2) on |0>.
    //     Only sincos(a/4) from MUFU; sin/cos(a/2) by double-angle. ---
    const float4* x4 = reinterpret_cast<const float4*>(x) + (long)st * 6;
    float u0r[6], u0i[6], u1r[6], u1i[6];
#pragma unroll
    for (int q = 0; q < 6; q++) {
        float4 v = __ldg(&x4[q]);
        float a = (v.x + v.y + v.z + v.w) * 0.25f;
        a = fminf(6.0f, fmaxf(-6.0f, a)) * (3.14159265358979323846f / 6.0f);
        float s4, c4;
        __sincosf(a * 0.25f, &s4, &c4);
        float s2 = 2.0f * s4 * c4;             // sin(a/2)
        float c2 = fmaf(-2.0f * s4, s4, 1.0f); // cos(a/2)
        u0r[q] = c2 * c4;  u0i[q] = -c2 * s4;
        u1r[q] = s2 * s4;  u1i[q] = -s2 * c4;
    }

    // --- product state: scalar factor for (q0=t1, q1=t0), then lane=q5,
    //     then double packs over q4 (bit0), q3 (bit1), q2 (bit2) ---
    float ar0 = t1 ? u1r[0] : u0r[0],  ai0 = t1 ? u1i[0] : u0i[0];
    float ar1 = t0 ? u1r[1] : u0r[1],  ai1 = t0 ? u1i[1] : u0i[1];
    float cr = ar0 * ar1 - ai0 * ai1;
    float ci = ar0 * ai1 + ai0 * ar1;
    u64 R[8], I[8];
    R[0] = pk2(cr * u0r[5] - ci * u0i[5], cr * u1r[5] - ci * u1i[5]);
    I[0] = pk2(cr * u0i[5] + ci * u0r[5], cr * u1i[5] + ci * u1r[5]);
#pragma unroll
    for (int qq = 0; qq < 3; qq++) {
        int q = 4 - qq;       // 4,3,2
        int n2 = 1 << qq;     // 1,2,4
        u64 a0 = bc2(u0r[q]), b0 = bc2(u0i[q]), nb0 = bc2(-u0i[q]);
        u64 a1 = bc2(u1r[q]), b1 = bc2(u1i[q]), nb1 = bc2(-u1i[q]);
#pragma unroll
        for (int j = 0; j < 4; j++) {
            if (j < n2) {  // constant-folds under full unroll
                u64 tr = R[j], ti = I[j];
                R[j + n2] = f2fma(nb1, ti, f2mul(a1, tr));
                I[j + n2] = f2fma(b1, tr, f2mul(a1, ti));
                R[j]      = f2fma(nb0, ti, f2mul(a0, tr));
                I[j]      = f2fma(b0, tr, f2mul(a0, ti));
            }
        }
    }

    // --- 3 layers; CNOT(0,1) relabel parity alternates 1,0,1 ---
    layer<1>(R, I, g_u + 0,  t0, t1);
    layer<0>(R, I, g_u + 48, t0, t1);
    layer<1>(R, I, g_u + 96, t0, t1);

    // --- measurements (final mapping: q0=t1, q1=t0^t1) ---
    u64 aS = 0, az2 = 0, az4 = 0, ax1 = 0, ax3 = 0, ax5 = 0;
#pragma unroll
    for (int p = 0; p < 8; p++) {
        u64 pr = f2fma(I[p], I[p], f2mul(R[p], R[p]));
        aS  = f2add(aS, pr);
        az2 = f2add(az2, (p & 4) ? (pr ^ SGN2) : pr);
        az4 = f2add(az4, (p & 1) ? (pr ^ SGN2) : pr);
        if (!(p & 2)) ax3 = f2fma(R[p], R[p | 2], f2fma(I[p], I[p | 2], ax3));
        ax5 = f2fma(R[p], f2swap(R[p]), f2fma(I[p], f2swap(I[p]), ax5));
        u64 PR = __shfl_xor_sync(0xffffffffu, R[p], 1);
        u64 PI = __shfl_xor_sync(0xffffffffu, I[p], 1);
        ax1 = f2fma(R[p], PR, f2fma(I[p], PI, ax1));
    }
    float lo, hi;
    upk2(aS,  lo, hi); float S0 = lo + hi;
    float z0 = t1 ? -S0 : S0;
    upk2(az2, lo, hi); float z2 = lo + hi;
    upk2(az4, lo, hi); float z4 = lo + hi;
    upk2(ax1, lo, hi); float x1 = lo + hi;   // pairs double-counted = the 2x
    upk2(ax3, lo, hi); float x3 = lo + hi;
    upk2(ax5, lo, hi); float x5 = lo;        // both lanes hold the same sum

    // reduce across the 4-thread group
    z0 += __shfl_xor_sync(0xffffffffu, z0, 1); z0 += __shfl_xor_sync(0xffffffffu, z0, 2);
    z2 += __shfl_xor_sync(0xffffffffu, z2, 1); z2 += __shfl_xor_sync(0xffffffffu, z2, 2);
    z4 += __shfl_xor_sync(0xffffffffu, z4, 1); z4 += __shfl_xor_sync(0xffffffffu, z4, 2);
    x1 += __shfl_xor_sync(0xffffffffu, x1, 1); x1 += __shfl_xor_sync(0xffffffffu, x1, 2);
    x3 += __shfl_xor_sync(0xffffffffu, x3, 1); x3 += __shfl_xor_sync(0xffffffffu, x3, 2);
    x5 += __shfl_xor_sync(0xffffffffu, x5, 1); x5 += __shfl_xor_sync(0xffffffffu, x5, 2);
    x3 *= 2.0f; x5 *= 2.0f;

    if (t == 0) {
        float4* o4 = reinterpret_cast<float4*>(out) + (long)st * 2;
        o4[0] = make_float4(z0, x1, z2, x3);
        o4[1] = make_float4(z4, x5, z0, x1);
    }
}

extern "C" void kernel_launch(void* const* d_in, const int* in_sizes, int n_in,
                              void* d_out, int out_size) {
    const float* x     = (const float*)d_in[0];
    const float* theta = (const float*)d_in[1];
    float* out = (float*)d_out;
    int Bn = in_sizes[0] / 24;

    prep_kernel<<<1, 32>>>(theta);
    long threads = 4L * Bn;
    int blocks = (int)((threads + 127) / 128);
    qsim_kernel<<<blocks, 128>>>(x, out, Bn);
}

// round 10
// speedup vs baseline: 2.0700x; 1.1195x over previous
#include <cuda_runtime.h>

// ---------------------------------------------------------------------------
// 6-qubit, 3-layer circuit, B=131072. FOUR threads per state (t1=q0, t0=q1),
// each holding 8 packed-f32x2 real + 8 imag regs (lane = q5; pack bits
// 2..0 = q2,q3,q4). Layers 1-2 as in round 7/9. Layer 3: only the CNOT ring's
// C(0,1) relabel + C(1,2) SELs + C(2,3),C(3,4) renames are applied; C(4,5),
// C(5,0) and ALL six layer-3 SU(2) gates are absorbed into the measurement
// observables via exact Heisenberg conjugation:
//   O_q -> U_q† O_q U_q = n·sigma ;  CNOTs map Paulis to Pauli products:
//   O~0 = nx X0 + ny Z4Z5Y0 + nz Z4Z5Z0
//   O~1 = nx X1 + ny Y1     + nz Z1
//   O~2,O~3 plain; O~4 = nx X4X5 + ny Y4X5 + nz Z4
//   O~5 = nx X5X0 + ny Z4Y5X0 + nz Z4Z5
// ---------------------------------------------------------------------------

typedef unsigned long long u64;
#define SGN2 0x8000000080000000ULL

__device__ __forceinline__ u64 pk2(float a, float b) {
    u64 r; asm("mov.b64 %0,{%1,%2};" : "=l"(r) : "f"(a), "f"(b)); return r;
}
__device__ __forceinline__ void upk2(u64 v, float& a, float& b) {
    asm("mov.b64 {%0,%1},%2;" : "=f"(a), "=f"(b) : "l"(v));
}
__device__ __forceinline__ u64 bc2(float a) { return pk2(a, a); }
__device__ __forceinline__ u64 f2mul(u64 a, u64 b) {
    u64 d; asm("mul.rn.f32x2 %0,%1,%2;" : "=l"(d) : "l"(a), "l"(b)); return d;
}
__device__ __forceinline__ u64 f2fma(u64 a, u64 b, u64 c) {
    u64 d; asm("fma.rn.f32x2 %0,%1,%2,%3;" : "=l"(d) : "l"(a), "l"(b), "l"(c)); return d;
}
__device__ __forceinline__ u64 f2add(u64 a, u64 b) {
    u64 d; asm("add.rn.f32x2 %0,%1,%2;" : "=l"(d) : "l"(a), "l"(b)); return d;
}
__device__ __forceinline__ u64 f2swap(u64 a) {
    u64 d;
    asm("{\n\t.reg .b32 x,y;\n\tmov.b64 {x,y},%1;\n\tmov.b64 %0,{y,x};\n\t}"
        : "=l"(d) : "l"(a));
    return d;
}

// Fused per-(l,q) SU(2) unitary U = Rz*Ry*Rx for layers 0,1 only.
__device__ u64 g_u[2 * 48];
// Measurement combine constants per qubit: [cx, cy, cz, 0]
__device__ float g_m[6 * 4];

__global__ void prep_kernel(const float* __restrict__ theta) {
    int t = threadIdx.x;
    if (t < 18) {
        int l = t / 6, q = t % 6;
        const float* th = theta + t * 3;
        float sx, cx, sy, cy, sz, cz;
        __sincosf(th[0] * 0.5f, &sx, &cx);
        __sincosf(th[1] * 0.5f, &sy, &cy);
        __sincosf(th[2] * 0.5f, &sz, &cz);
        float m00r =  cy * cx, m00i =  sy * sx;
        float m01r = -sy * cx, m01i = -cy * sx;
        float ar = cz * m00r + sz * m00i, ai = cz * m00i - sz * m00r;
        float br = cz * m01r + sz * m01i, bi = cz * m01i - sz * m01r;
        if (l < 2) {
            u64* g = g_u + l * 48;
            if (q == 0) {
                g[0] = bc2(ar); g[1] = bc2(ai); g[2] = bc2(br);
                g[3] = bc2(bi); g[4] = bc2(-bi);
            } else if (q == 1) {
                g[8] = bc2(ar); g[9] = bc2(ai); g[10] = bc2(br); g[11] = bc2(bi);
            } else if (q < 5) {
                u64* h = g + 16 + (q - 2) * 8;
                h[0] = bc2(ar); h[1] = bc2(ai); h[2] = bc2(-ai);
                h[3] = bc2(br); h[4] = bc2(-br); h[5] = bc2(bi); h[6] = bc2(-bi);
            } else {
                u64* h = g + 40;
                h[0] = pk2(ar, ar);   h[1] = pk2(-ai, ai);
                h[2] = pk2(br, -br);  h[3] = pk2(-bi, -bi);
                h[4] = pk2(ai, -ai);  h[5] = pk2(bi, bi);
            }
        } else {
            // layer 3: observable n-vector. even q: U†ZU, odd q: U†XU
            float nx, ny, nz;
            if ((q & 1) == 0) {
                nz = (ar * ar + ai * ai) - (br * br + bi * bi);
                nx = 2.0f * (br * ar + bi * ai);
                ny = 2.0f * (br * ai - bi * ar);
            } else {
                nz = -2.0f * (ar * br - ai * bi);
                nx = ar * ar - ai * ai - br * br + bi * bi;
                ny = 2.0f * (ar * ai + br * bi);
            }
            // fold constant 2x factors of the local-qubit cross sums
            if (q == 2 || q == 3) { nx *= 2.0f; ny *= 2.0f; }
            if (q == 4) { ny *= 2.0f; }
            g_m[q * 4 + 0] = nx;
            g_m[q * 4 + 1] = ny;
            g_m[q * 4 + 2] = nz;
        }
    }
}

// Local SU(2) on a pack bit (MP = 4 -> q2, 2 -> q3, 1 -> q4).
template <int MP>
__device__ __forceinline__ void su2_loc(u64* R, u64* I, const u64* __restrict__ u) {
    u64 ar = u[0], ai = u[1], nai = u[2];
    u64 br = u[3], nbr = u[4], bi = u[5], nbi = u[6];
#pragma unroll
    for (int g = 0; g < 4; g++) {
        int p0 = (g & (MP - 1)) | ((g & ~(MP - 1)) << 1);
        int p1 = p0 | MP;
        u64 Ar = R[p0], Ai = I[p0], Br = R[p1], Bi = I[p1];
        R[p0] = f2fma(nbi, Bi, f2fma(br, Br, f2fma(nai, Ai, f2mul(ar, Ar))));
        I[p0] = f2fma(br, Bi, f2fma(bi, Br, f2fma(ai, Ar, f2mul(ar, Ai))));
        R[p1] = f2fma(ai, Bi, f2fma(ar, Br, f2fma(nbi, Ai, f2mul(nbr, Ar))));
        I[p1] = f2fma(nai, Br, f2fma(ar, Bi, f2fma(bi, Ar, f2mul(nbr, Ai))));
    }
}

// Local SU(2) on qubit 5 (lane), within-pack butterfly via half-swap.
__device__ __forceinline__ void su2_q5(u64* R, u64* I, const u64* __restrict__ u) {
    u64 aa = u[0], am = u[1], bp = u[2], nb2 = u[3], ap = u[4], bb = u[5];
#pragma unroll
    for (int p = 0; p < 8; p++) {
        u64 r = R[p], m = I[p];
        u64 sr = f2swap(r), sm = f2swap(m);
        R[p] = f2fma(nb2, sm, f2fma(bp, sr, f2fma(am, m, f2mul(aa, r))));
        I[p] = f2fma(bb, sr, f2fma(bp, sm, f2fma(ap, r, f2mul(aa, m))));
    }
}

__device__ __forceinline__ void swp(u64* A, int i, int j) {
    u64 t = A[i]; A[i] = A[j]; A[j] = t;
}

// One layer (layers 0,1). S = mapping AFTER this layer's CNOT(0,1) relabel:
//   S=1: q0=t1, q1=t0^t1 ; S=0: q0=t1, q1=t0.
template <int S>
__device__ __forceinline__ void layer(u64* R, u64* I, const u64* __restrict__ cf,
                                      int t0, int t1) {
    int q1log = S ? (t0 ^ t1) : t0;
    bool c = (q1log != 0);
#pragma unroll
    for (int p = 0; p < 4; p++) {
        u64 a = R[p], b = R[p + 4];
        R[p] = c ? b : a;  R[p + 4] = c ? a : b;
        a = I[p]; b = I[p + 4];
        I[p] = c ? b : a;  I[p + 4] = c ? a : b;
    }
    swp(R, 4, 6); swp(R, 5, 7); swp(I, 4, 6); swp(I, 5, 7);
    swp(R, 2, 3); swp(R, 6, 7); swp(I, 2, 3); swp(I, 6, 7);

    // q0 gate (cross-thread), CNOT(4,5) + CNOT(5,0) folded into the gather.
    {
        u64 smask = t1 ? SGN2 : 0ULL;
        u64 car  = cf[0];
        u64 cai  = cf[1] ^ smask;
        u64 ncai = cai ^ SGN2;
        u64 cbr  = cf[2] ^ smask;
        u64 cbi  = cf[3];
        u64 ncbi = cf[4];
        constexpr int PX = S ? 3 : 2;
#pragma unroll
        for (int p = 0; p < 8; p++) {
            u64 LR = R[p], LI = I[p];
            u64 MR = __shfl_xor_sync(0xffffffffu, LR, PX);
            u64 MI = __shfl_xor_sync(0xffffffffu, LI, PX);
            float lr0, lr1, li0, li1, mr0, mr1, mi0, mi1;
            upk2(LR, lr0, lr1); upk2(LI, li0, li1);
            upk2(MR, mr0, mr1); upk2(MI, mi0, mi1);
            u64 AR, AI, BR, BI;
            if ((p & 1) == 0) {
                AR = pk2(lr0, mr1); AI = pk2(li0, mi1);
                BR = pk2(mr0, lr1); BI = pk2(mi0, li1);
            } else {
                AR = pk2(lr1, mr0); AI = pk2(li1, mi0);
                BR = pk2(mr1, lr0); BI = pk2(mi1, li0);
            }
            R[p] = f2fma(ncbi, BI, f2fma(cbr, BR, f2fma(ncai, AI, f2mul(car, AR))));
            I[p] = f2fma(cbi, BR, f2fma(cbr, BI, f2fma(cai, AR, f2mul(car, AI))));
        }
    }

    // q1 gate (cross-thread, partner xor 1, role = q1log)
    {
        u64 m1   = q1log ? SGN2 : 0ULL;
        u64 ar   = cf[8];
        u64 cai  = cf[9] ^ m1;
        u64 ncai = cai ^ SGN2;
        u64 cbr  = cf[10] ^ m1;
        u64 bi   = cf[11];
        u64 nbi  = bi ^ SGN2;
#pragma unroll
        for (int p = 0; p < 8; p++) {
            u64 LR = R[p], LI = I[p];
            u64 MR = __shfl_xor_sync(0xffffffffu, LR, 1);
            u64 MI = __shfl_xor_sync(0xffffffffu, LI, 1);
            R[p] = f2fma(nbi, MI, f2fma(cbr, MR, f2fma(ncai, LI, f2mul(ar, LR))));
            I[p] = f2fma(bi, MR, f2fma(cbr, MI, f2fma(cai, LR, f2mul(ar, LI))));
        }
    }

    su2_loc<4>(R, I, cf + 16);
    su2_loc<2>(R, I, cf + 24);
    su2_loc<1>(R, I, cf + 32);
    su2_q5(R, I, cf + 40);
}

__global__ __launch_bounds__(128, 6) void qsim_kernel(
    const float* __restrict__ x, float* __restrict__ out, int Bn)
{
    int gid = blockIdx.x * 128 + threadIdx.x;
    int st = gid >> 2;
    if (st >= Bn) return;
    int t = gid & 3;
    int t0 = t & 1, t1 = (t >> 1) & 1;

    // --- encoding (1 sincos per qubit; double-angle for a/2 terms) ---
    const float4* x4 = reinterpret_cast<const float4*>(x) + (long)st * 6;
    float u0r[6], u0i[6], u1r[6], u1i[6];
#pragma unroll
    for (int q = 0; q < 6; q++) {
        float4 v = __ldg(&x4[q]);
        float a = (v.x + v.y + v.z + v.w) * 0.25f;
        a = fminf(6.0f, fmaxf(-6.0f, a)) * (3.14159265358979323846f / 6.0f);
        float s4, c4;
        __sincosf(a * 0.25f, &s4, &c4);
        float s2 = 2.0f * s4 * c4;
        float c2 = fmaf(-2.0f * s4, s4, 1.0f);
        u0r[q] = c2 * c4;  u0i[q] = -c2 * s4;
        u1r[q] = s2 * s4;  u1i[q] = -s2 * c4;
    }

    // --- product state ---
    float ar0 = t1 ? u1r[0] : u0r[0],  ai0 = t1 ? u1i[0] : u0i[0];
    float ar1 = t0 ? u1r[1] : u0r[1],  ai1 = t0 ? u1i[1] : u0i[1];
    float cr = ar0 * ar1 - ai0 * ai1;
    float ci = ar0 * ai1 + ai0 * ar1;
    u64 R[8], I[8];
    R[0] = pk2(cr * u0r[5] - ci * u0i[5], cr * u1r[5] - ci * u1i[5]);
    I[0] = pk2(cr * u0i[5] + ci * u0r[5], cr * u1i[5] + ci * u1r[5]);
#pragma unroll
    for (int qq = 0; qq < 3; qq++) {
        int q = 4 - qq;
        int n2 = 1 << qq;
        u64 a0 = bc2(u0r[q]), b0 = bc2(u0i[q]), nb0 = bc2(-u0i[q]);
        u64 a1 = bc2(u1r[q]), b1 = bc2(u1i[q]), nb1 = bc2(-u1i[q]);
#pragma unroll
        for (int j = 0; j < 4; j++) {
            if (j < n2) {
                u64 tr = R[j], ti = I[j];
                R[j + n2] = f2fma(nb1, ti, f2mul(a1, tr));
                I[j + n2] = f2fma(b1, tr, f2mul(a1, ti));
                R[j]      = f2fma(nb0, ti, f2mul(a0, tr));
                I[j]      = f2fma(b0, tr, f2mul(a0, ti));
            }
        }
    }

    // --- layers 1,2 (full); layer 3: CNOT ring prefix only ---
    layer<1>(R, I, g_u + 0,  t0, t1);
    layer<0>(R, I, g_u + 48, t0, t1);
    {
        // L3 relabel S=1: q0=t1, q1=t0^t1. CNOT(1,2) SEL; C23,C34 renames.
        bool c = ((t0 ^ t1) != 0);
#pragma unroll
        for (int p = 0; p < 4; p++) {
            u64 a = R[p], b = R[p + 4];
            R[p] = c ? b : a;  R[p + 4] = c ? a : b;
            a = I[p]; b = I[p + 4];
            I[p] = c ? b : a;  I[p + 4] = c ? a : b;
        }
        swp(R, 4, 6); swp(R, 5, 7); swp(I, 4, 6); swp(I, 5, 7);
        swp(R, 2, 3); swp(R, 6, 7); swp(I, 2, 3); swp(I, 6, 7);
        // C45, C50 and all layer-3 gates: absorbed into observables below.
    }

    // --- measurements on the pre-C45/C50 state ---
    u64 aS = 0, az2 = 0, az3 = 0, az4 = 0;
    u64 ex2 = 0, ey2 = 0, ex3 = 0, ey3 = 0, x45 = 0, y45 = 0;
    u64 ax0 = 0, zy0 = 0, x50 = 0, zyx = 0, ax1 = 0, ay1 = 0;
#pragma unroll
    for (int p = 0; p < 8; p++) {
        u64 pr = f2fma(I[p], I[p], f2mul(R[p], R[p]));
        aS  = f2add(aS, pr);
        az2 = f2add(az2, (p & 4) ? (pr ^ SGN2) : pr);
        az3 = f2add(az3, (p & 2) ? (pr ^ SGN2) : pr);
        az4 = f2add(az4, (p & 1) ? (pr ^ SGN2) : pr);
        if (!(p & 4)) {
            ex2 = f2fma(R[p], R[p | 4], f2fma(I[p], I[p | 4], ex2));
            ey2 = f2fma(R[p], I[p | 4], f2fma(I[p] ^ SGN2, R[p | 4], ey2));
        }
        if (!(p & 2)) {
            ex3 = f2fma(R[p], R[p | 2], f2fma(I[p], I[p | 2], ex3));
            ey3 = f2fma(R[p], I[p | 2], f2fma(I[p] ^ SGN2, R[p | 2], ey3));
        }
        x45 = f2fma(R[p], f2swap(R[p ^ 1]), f2fma(I[p], f2swap(I[p ^ 1]), x45));
        if (!(p & 1)) {
            y45 = f2fma(R[p], f2swap(I[p | 1]),
                        f2fma(I[p] ^ SGN2, f2swap(R[p | 1]), y45));
        }
        // q0 round: partner flips logical q0 only -> lane xor 3
        u64 PR = __shfl_xor_sync(0xffffffffu, R[p], 3);
        u64 PI = __shfl_xor_sync(0xffffffffu, I[p], 3);
        ax0 = f2fma(R[p], PR, f2fma(I[p], PI, ax0));
        {
            u64 v = f2fma(R[p], PI, f2mul(I[p] ^ SGN2, PR));
            zy0 = f2add(zy0, (p & 1) ? (v ^ SGN2) : v);
        }
        x50 = f2fma(R[p], f2swap(PR), f2fma(I[p], f2swap(PI), x50));
        {
            u64 v = f2fma(R[p], f2swap(PI), f2mul(I[p] ^ SGN2, f2swap(PR)));
            zyx = f2add(zyx, (p & 1) ? (v ^ SGN2) : v);
        }
        // q1 round: partner flips logical q1 only -> lane xor 1
        u64 QR = __shfl_xor_sync(0xffffffffu, R[p], 1);
        u64 QI = __shfl_xor_sync(0xffffffffu, I[p], 1);
        ax1 = f2fma(R[p], QR, f2fma(I[p], QI, ax1));
        ay1 = f2fma(R[p], QI, f2fma(I[p] ^ SGN2, QR, ay1));
    }

    float lo, hi;
    upk2(aS,  lo, hi); float sAll = lo + hi;
    upk2(az2, lo, hi); float sZ2  = lo + hi;
    upk2(az3, lo, hi); float sZ3  = lo + hi;
    upk2(az4, lo, hi); float sZ4  = lo + hi, sZ45 = lo - hi;
    upk2(ex2, lo, hi); float sEx2 = lo + hi;
    upk2(ey2, lo, hi); float sEy2 = lo + hi;
    upk2(ex3, lo, hi); float sEx3 = lo + hi;
    upk2(ey3, lo, hi); float sEy3 = lo + hi;
    upk2(x45, lo, hi); float sX45 = lo + hi;
    upk2(y45, lo, hi); float sY45 = lo + hi;
    upk2(ax0, lo, hi); float sX0  = lo + hi;
    upk2(zy0, lo, hi); float sZY0 = lo - hi;
    upk2(x50, lo, hi); float sX50 = lo + hi;
    upk2(zyx, lo, hi); float sZYX = lo - hi;
    upk2(ax1, lo, hi); float sX1  = lo + hi;
    upk2(ay1, lo, hi); float sY1  = lo + hi;

    float sgT = t1 ? -1.0f : 1.0f;          // q0 role sign
    float sg1 = ((t0 ^ t1) != 0) ? -1.0f : 1.0f;  // q1 role sign

    float m0 = g_m[2]  * (sgT * sZ45) + g_m[0]  * sX0  + g_m[1]  * (sgT * sZY0);
    float m1 = g_m[6]  * (sg1 * sAll) + g_m[4]  * sX1  + g_m[5]  * (sg1 * sY1);
    float m2 = g_m[10] * sZ2          + g_m[8]  * sEx2 + g_m[9]  * sEy2;
    float m3 = g_m[14] * sZ3          + g_m[12] * sEx3 + g_m[13] * sEy3;
    float m4 = g_m[18] * sZ4          + g_m[16] * sX45 + g_m[17] * sY45;
    float m5 = g_m[22] * sZ45         + g_m[20] * sX50 + g_m[21] * sZYX;

    // reduce across the 4-thread group
    m0 += __shfl_xor_sync(0xffffffffu, m0, 1); m0 += __shfl_xor_sync(0xffffffffu, m0, 2);
    m1 += __shfl_xor_sync(0xffffffffu, m1, 1); m1 += __shfl_xor_sync(0xffffffffu, m1, 2);
    m2 += __shfl_xor_sync(0xffffffffu, m2, 1); m2 += __shfl_xor_sync(0xffffffffu, m2, 2);
    m3 += __shfl_xor_sync(0xffffffffu, m3, 1); m3 += __shfl_xor_sync(0xffffffffu, m3, 2);
    m4 += __shfl_xor_sync(0xffffffffu, m4, 1); m4 += __shfl_xor_sync(0xffffffffu, m4, 2);
    m5 += __shfl_xor_sync(0xffffffffu, m5, 1); m5 += __shfl_xor_sync(0xffffffffu, m5, 2);

    if (t == 0) {
        float4* o4 = reinterpret_cast<float4*>(out) + (long)st * 2;
        o4[0] = make_float4(m0, m1, m2, m3);
        o4[1] = make_float4(m4, m5, m0, m1);
    }
}

extern "C" void kernel_launch(void* const* d_in, const int* in_sizes, int n_in,
                              void* d_out, int out_size) {
    const float* x     = (const float*)d_in[0];
    const float* theta = (const float*)d_in[1];
    float* out = (float*)d_out;
    int Bn = in_sizes[0] / 24;

    prep_kernel<<<1, 32>>>(theta);
    long threads = 4L * Bn;
    int blocks = (int)((threads + 127) / 128);
    qsim_kernel<<<blocks, 128>>>(x, out, Bn);
}

// round 11
// speedup vs baseline: 2.3183x; 1.1200x over previous
#include <cuda_runtime.h>

// ---------------------------------------------------------------------------
// 6-qubit, 3-layer circuit, B=131072. FOUR threads per state (t1,t0 thread
// bits), each holding 8 packed-f32x2 real + 8 imag regs (lane = q5; pack bits
// 2..0 = q2,q3,q4).
//  * Layer-1 CNOT ring + its q0,q1 gates: absorbed ANALYTICALLY into the
//    initial build. ring(product) amplitude:
//      amp(y) = u0[y0^y5] u1[y0^y1^y5] u2[y1^y2] u3[y2^y3] u4[y3^y4] u5[y4^y5]
//    and U0 (y0=t1), U1 (y1=t0) applied via per-thread scalar contraction.
//  * Layer-1 q2..q5 gates: local packed butterflies (no shfl).
//  * Layer 2: full layer with C01 relabel (S=1), C12 SELs, C23/C34 renames,
//    C45+C50 folded into the q0-gate gather.
//  * Layer 3: C01 relabel (map -> q0=t1, q1=t0), C12 SEL (c=t0), C23/C34
//    renames; C45, C50 and all six gates absorbed into observables:
//      O~0 = nx X0 + ny Z4Z5Y0 + nz Z4Z5Z0 ; O~1 = nx X1 + ny Y1 + nz Z1
//      O~2,O~3 plain ; O~4 = nx X4X5 + ny Y4X5 + nz Z4
//      O~5 = nx X5X0 + ny Z4Y5X0 + nz Z4Z5
//    Measurement q0-partner = lane xor 2; q1-partner = xor 1.
// ---------------------------------------------------------------------------

typedef unsigned long long u64;
#define SGN2 0x8000000080000000ULL

__device__ __forceinline__ u64 pk2(float a, float b) {
    u64 r; asm("mov.b64 %0,{%1,%2};" : "=l"(r) : "f"(a), "f"(b)); return r;
}
__device__ __forceinline__ void upk2(u64 v, float& a, float& b) {
    asm("mov.b64 {%0,%1},%2;" : "=f"(a), "=f"(b) : "l"(v));
}
__device__ __forceinline__ u64 bc2(float a) { return pk2(a, a); }
__device__ __forceinline__ u64 f2mul(u64 a, u64 b) {
    u64 d; asm("mul.rn.f32x2 %0,%1,%2;" : "=l"(d) : "l"(a), "l"(b)); return d;
}
__device__ __forceinline__ u64 f2fma(u64 a, u64 b, u64 c) {
    u64 d; asm("fma.rn.f32x2 %0,%1,%2,%3;" : "=l"(d) : "l"(a), "l"(b), "l"(c)); return d;
}
__device__ __forceinline__ u64 f2add(u64 a, u64 b) {
    u64 d; asm("add.rn.f32x2 %0,%1,%2;" : "=l"(d) : "l"(a), "l"(b)); return d;
}
__device__ __forceinline__ u64 f2swap(u64 a) {
    u64 d;
    asm("{\n\t.reg .b32 x,y;\n\tmov.b64 {x,y},%1;\n\tmov.b64 %0,{y,x};\n\t}"
        : "=l"(d) : "l"(a));
    return d;
}

// Broadcast tables: layer0 slots 16..45 (q2..q5 only), layer1 full 48.
__device__ u64 g_u[2 * 48];
// Layer-1 q0,q1 raw SU(2) coefficients: [a0r,a0i,b0r,b0i, a1r,a1i,b1r,b1i]
__device__ float g_l1[8];
// Observable combine constants per qubit: [cx, cy, cz, 0]
__device__ float g_m[6 * 4];

__global__ void prep_kernel(const float* __restrict__ theta) {
    int t = threadIdx.x;
    if (t < 18) {
        int l = t / 6, q = t % 6;
        const float* th = theta + t * 3;
        float sx, cx, sy, cy, sz, cz;
        __sincosf(th[0] * 0.5f, &sx, &cx);
        __sincosf(th[1] * 0.5f, &sy, &cy);
        __sincosf(th[2] * 0.5f, &sz, &cz);
        float m00r =  cy * cx, m00i =  sy * sx;
        float m01r = -sy * cx, m01i = -cy * sx;
        float ar = cz * m00r + sz * m00i, ai = cz * m00i - sz * m00r;
        float br = cz * m01r + sz * m01i, bi = cz * m01i - sz * m01r;
        if (l < 2) {
            u64* g = g_u + l * 48;
            if (q == 0) {
                if (l == 0) {
                    g_l1[0] = ar; g_l1[1] = ai; g_l1[2] = br; g_l1[3] = bi;
                } else {
                    g[0] = bc2(ar); g[1] = bc2(ai); g[2] = bc2(br);
                    g[3] = bc2(bi); g[4] = bc2(-bi);
                }
            } else if (q == 1) {
                if (l == 0) {
                    g_l1[4] = ar; g_l1[5] = ai; g_l1[6] = br; g_l1[7] = bi;
                } else {
                    g[8] = bc2(ar); g[9] = bc2(ai); g[10] = bc2(br); g[11] = bc2(bi);
                }
            } else if (q < 5) {
                u64* h = g + 16 + (q - 2) * 8;
                h[0] = bc2(ar); h[1] = bc2(ai); h[2] = bc2(-ai);
                h[3] = bc2(br); h[4] = bc2(-br); h[5] = bc2(bi); h[6] = bc2(-bi);
            } else {
                u64* h = g + 40;
                h[0] = pk2(ar, ar);   h[1] = pk2(-ai, ai);
                h[2] = pk2(br, -br);  h[3] = pk2(-bi, -bi);
                h[4] = pk2(ai, -ai);  h[5] = pk2(bi, bi);
            }
        } else {
            // layer 3: observable n-vector. even q: U†ZU, odd q: U†XU
            float nx, ny, nz;
            if ((q & 1) == 0) {
                nz = (ar * ar + ai * ai) - (br * br + bi * bi);
                nx = 2.0f * (br * ar + bi * ai);
                ny = 2.0f * (br * ai - bi * ar);
            } else {
                nz = -2.0f * (ar * br - ai * bi);
                nx = ar * ar - ai * ai - br * br + bi * bi;
                ny = 2.0f * (ar * ai + br * bi);
            }
            if (q == 2 || q == 3) { nx *= 2.0f; ny *= 2.0f; }
            if (q == 4) { ny *= 2.0f; }
            g_m[q * 4 + 0] = nx;
            g_m[q * 4 + 1] = ny;
            g_m[q * 4 + 2] = nz;
        }
    }
}

// Local SU(2) on a pack bit (MP = 4 -> q2, 2 -> q3, 1 -> q4).
template <int MP>
__device__ __forceinline__ void su2_loc(u64* R, u64* I, const u64* __restrict__ u) {
    u64 ar = u[0], ai = u[1], nai = u[2];
    u64 br = u[3], nbr = u[4], bi = u[5], nbi = u[6];
#pragma unroll
    for (int g = 0; g < 4; g++) {
        int p0 = (g & (MP - 1)) | ((g & ~(MP - 1)) << 1);
        int p1 = p0 | MP;
        u64 Ar = R[p0], Ai = I[p0], Br = R[p1], Bi = I[p1];
        R[p0] = f2fma(nbi, Bi, f2fma(br, Br, f2fma(nai, Ai, f2mul(ar, Ar))));
        I[p0] = f2fma(br, Bi, f2fma(bi, Br, f2fma(ai, Ar, f2mul(ar, Ai))));
        R[p1] = f2fma(ai, Bi, f2fma(ar, Br, f2fma(nbi, Ai, f2mul(nbr, Ar))));
        I[p1] = f2fma(nai, Br, f2fma(ar, Bi, f2fma(bi, Ar, f2mul(nbr, Ai))));
    }
}

// Local SU(2) on qubit 5 (lane), within-pack butterfly via half-swap.
__device__ __forceinline__ void su2_q5(u64* R, u64* I, const u64* __restrict__ u) {
    u64 aa = u[0], am = u[1], bp = u[2], nb2 = u[3], ap = u[4], bb = u[5];
#pragma unroll
    for (int p = 0; p < 8; p++) {
        u64 r = R[p], m = I[p];
        u64 sr = f2swap(r), sm = f2swap(m);
        R[p] = f2fma(nb2, sm, f2fma(bp, sr, f2fma(am, m, f2mul(aa, r))));
        I[p] = f2fma(bb, sr, f2fma(bp, sm, f2fma(ap, r, f2mul(aa, m))));
    }
}

__device__ __forceinline__ void swp(u64* A, int i, int j) {
    u64 t = A[i]; A[i] = A[j]; A[j] = t;
}

// Full layer (used for layer 2). S=1 mapping AFTER C01 relabel: q0=t1, q1=t0^t1.
template <int S>
__device__ __forceinline__ void layer(u64* R, u64* I, const u64* __restrict__ cf,
                                      int t0, int t1) {
    int q1log = S ? (t0 ^ t1) : t0;
    bool c = (q1log != 0);
#pragma unroll
    for (int p = 0; p < 4; p++) {
        u64 a = R[p], b = R[p + 4];
        R[p] = c ? b : a;  R[p + 4] = c ? a : b;
        a = I[p]; b = I[p + 4];
        I[p] = c ? b : a;  I[p + 4] = c ? a : b;
    }
    swp(R, 4, 6); swp(R, 5, 7); swp(I, 4, 6); swp(I, 5, 7);
    swp(R, 2, 3); swp(R, 6, 7); swp(I, 2, 3); swp(I, 6, 7);

    // q0 gate (cross-thread), CNOT(4,5) + CNOT(5,0) folded into the gather.
    {
        u64 smask = t1 ? SGN2 : 0ULL;
        u64 car  = cf[0];
        u64 cai  = cf[1] ^ smask;
        u64 ncai = cai ^ SGN2;
        u64 cbr  = cf[2] ^ smask;
        u64 cbi  = cf[3];
        u64 ncbi = cf[4];
        constexpr int PX = S ? 3 : 2;
#pragma unroll
        for (int p = 0; p < 8; p++) {
            u64 LR = R[p], LI = I[p];
            u64 MR = __shfl_xor_sync(0xffffffffu, LR, PX);
            u64 MI = __shfl_xor_sync(0xffffffffu, LI, PX);
            float lr0, lr1, li0, li1, mr0, mr1, mi0, mi1;
            upk2(LR, lr0, lr1); upk2(LI, li0, li1);
            upk2(MR, mr0, mr1); upk2(MI, mi0, mi1);
            u64 AR, AI, BR, BI;
            if ((p & 1) == 0) {
                AR = pk2(lr0, mr1); AI = pk2(li0, mi1);
                BR = pk2(mr0, lr1); BI = pk2(mi0, li1);
            } else {
                AR = pk2(lr1, mr0); AI = pk2(li1, mi0);
                BR = pk2(mr1, lr0); BI = pk2(mi1, li0);
            }
            R[p] = f2fma(ncbi, BI, f2fma(cbr, BR, f2fma(ncai, AI, f2mul(car, AR))));
            I[p] = f2fma(cbi, BR, f2fma(cbr, BI, f2fma(cai, AR, f2mul(car, AI))));
        }
    }

    // q1 gate (cross-thread, partner xor 1, role = q1log)
    {
        u64 m1   = q1log ? SGN2 : 0ULL;
        u64 ar   = cf[8];
        u64 cai  = cf[9] ^ m1;
        u64 ncai = cai ^ SGN2;
        u64 cbr  = cf[10] ^ m1;
        u64 bi   = cf[11];
        u64 nbi  = bi ^ SGN2;
#pragma unroll
        for (int p = 0; p < 8; p++) {
            u64 LR = R[p], LI = I[p];
            u64 MR = __shfl_xor_sync(0xffffffffu, LR, 1);
            u64 MI = __shfl_xor_sync(0xffffffffu, LI, 1);
            R[p] = f2fma(nbi, MI, f2fma(cbr, MR, f2fma(ncai, LI, f2mul(ar, LR))));
            I[p] = f2fma(bi, MR, f2fma(cbr, MI, f2fma(cai, LR, f2mul(ar, LI))));
        }
    }

    su2_loc<4>(R, I, cf + 16);
    su2_loc<2>(R, I, cf + 24);
    su2_loc<1>(R, I, cf + 32);
    su2_q5(R, I, cf + 40);
}

__global__ __launch_bounds__(128, 6) void qsim_kernel(
    const float* __restrict__ x, float* __restrict__ out, int Bn)
{
    int gid = blockIdx.x * 128 + threadIdx.x;
    int st = gid >> 2;
    if (st >= Bn) return;
    int t = gid & 3;
    int t0 = t & 1, t1 = (t >> 1) & 1;

    // --- encoding (1 sincos per qubit; double-angle for a/2 terms) ---
    const float4* x4 = reinterpret_cast<const float4*>(x) + (long)st * 6;
    float ur[6][2], ui[6][2];
#pragma unroll
    for (int q = 0; q < 6; q++) {
        float4 v = __ldg(&x4[q]);
        float a = (v.x + v.y + v.z + v.w) * 0.25f;
        a = fminf(6.0f, fmaxf(-6.0f, a)) * (3.14159265358979323846f / 6.0f);
        float s4, c4;
        __sincosf(a * 0.25f, &s4, &c4);
        float s2 = 2.0f * s4 * c4;
        float c2 = fmaf(-2.0f * s4, s4, 1.0f);
        ur[q][0] = c2 * c4;  ui[q][0] = -c2 * s4;
        ur[q][1] = s2 * s4;  ui[q][1] = -s2 * c4;
    }

    // --- build: ring1(product) with U0 (on y0=t1) and U1 (on y1=t0) absorbed.
    //     amp(y) = sum_{c0,c1} U0[t1,c0] U1[t0,c1] u0[c0^y5] u1[c0^c1^y5]
    //              u2[c1^y2] u3[y2^y3] u4[y3^y4] u5[y4^y5]
    float C0r, C0i, C1r, C1i, D0r, D0i, D1r, D1i;
    {
        float a0r = g_l1[0], a0i = g_l1[1], b0r = g_l1[2], b0i = g_l1[3];
        C0r = t1 ? -b0r : a0r;  C0i = t1 ?  b0i : a0i;
        C1r = t1 ?  a0r : b0r;  C1i = t1 ? -a0i : b0i;
        float a1r = g_l1[4], a1i = g_l1[5], b1r = g_l1[6], b1i = g_l1[7];
        D0r = t0 ? -b1r : a1r;  D0i = t0 ?  b1i : a1i;
        D1r = t0 ?  a1r : b1r;  D1i = t0 ? -a1i : b1i;
    }
    float Vr[2][2], Vi[2][2];  // [y2][y5]
    {
        float Tr[2][2], Ti[2][2];  // [c0][y5]
#pragma unroll
        for (int y5 = 0; y5 < 2; y5++) {
            Tr[0][y5] = C0r * ur[0][y5] - C0i * ui[0][y5];
            Ti[0][y5] = C0r * ui[0][y5] + C0i * ur[0][y5];
            Tr[1][y5] = C1r * ur[0][1 ^ y5] - C1i * ui[0][1 ^ y5];
            Ti[1][y5] = C1r * ui[0][1 ^ y5] + C1i * ur[0][1 ^ y5];
        }
        float Wr[2][2], Wi[2][2];  // [c1][y5]
#pragma unroll
        for (int c1 = 0; c1 < 2; c1++)
#pragma unroll
            for (int y5 = 0; y5 < 2; y5++) {
                int j = c1 ^ y5;
                Wr[c1][y5] = Tr[0][y5] * ur[1][j] - Ti[0][y5] * ui[1][j]
                           + Tr[1][y5] * ur[1][j ^ 1] - Ti[1][y5] * ui[1][j ^ 1];
                Wi[c1][y5] = Tr[0][y5] * ui[1][j] + Ti[0][y5] * ur[1][j]
                           + Tr[1][y5] * ui[1][j ^ 1] + Ti[1][y5] * ur[1][j ^ 1];
            }
        float Pr[2][2], Pi2[2][2];  // T2 [c1][y5]
#pragma unroll
        for (int y5 = 0; y5 < 2; y5++) {
            Pr[0][y5]  = D0r * Wr[0][y5] - D0i * Wi[0][y5];
            Pi2[0][y5] = D0r * Wi[0][y5] + D0i * Wr[0][y5];
            Pr[1][y5]  = D1r * Wr[1][y5] - D1i * Wi[1][y5];
            Pi2[1][y5] = D1r * Wi[1][y5] + D1i * Wr[1][y5];
        }
#pragma unroll
        for (int y2 = 0; y2 < 2; y2++)
#pragma unroll
            for (int y5 = 0; y5 < 2; y5++) {
                Vr[y2][y5] = Pr[0][y5] * ur[2][y2] - Pi2[0][y5] * ui[2][y2]
                           + Pr[1][y5] * ur[2][y2 ^ 1] - Pi2[1][y5] * ui[2][y2 ^ 1];
                Vi[y2][y5] = Pr[0][y5] * ui[2][y2] + Pi2[0][y5] * ur[2][y2]
                           + Pr[1][y5] * ui[2][y2 ^ 1] + Pi2[1][y5] * ur[2][y2 ^ 1];
            }
    }
    // packed over lane y5, expand y3 (pack bit1) via u3[y2^y3]
    u64 CRm[2][2], CIm[2][2];  // [y2][y3]
    {
        u64 BR[2], BI[2];
        BR[0] = pk2(Vr[0][0], Vr[0][1]); BI[0] = pk2(Vi[0][0], Vi[0][1]);
        BR[1] = pk2(Vr[1][0], Vr[1][1]); BI[1] = pk2(Vi[1][0], Vi[1][1]);
        u64 w3r[2], w3i[2], n3i[2];
        w3r[0] = bc2(ur[3][0]); w3i[0] = bc2(ui[3][0]); n3i[0] = bc2(-ui[3][0]);
        w3r[1] = bc2(ur[3][1]); w3i[1] = bc2(ui[3][1]); n3i[1] = bc2(-ui[3][1]);
#pragma unroll
        for (int y2 = 0; y2 < 2; y2++)
#pragma unroll
            for (int y3 = 0; y3 < 2; y3++) {
                int m = y2 ^ y3;
                CRm[y2][y3] = f2fma(n3i[m], BI[y2], f2mul(w3r[m], BR[y2]));
                CIm[y2][y3] = f2fma(w3i[m], BR[y2], f2mul(w3r[m], BI[y2]));
            }
    }
    // K[y3][y4] = packed (u4[y4^y3]*u5[y4], u4[y4^y3]*u5[1^y4]); expand y4
    u64 R[8], I[8];
    {
        float k45r[2][2], k45i[2][2];  // [m][n] = u4[m]*u5[n]
#pragma unroll
        for (int m = 0; m < 2; m++)
#pragma unroll
            for (int n = 0; n < 2; n++) {
                k45r[m][n] = ur[4][m] * ur[5][n] - ui[4][m] * ui[5][n];
                k45i[m][n] = ur[4][m] * ui[5][n] + ui[4][m] * ur[5][n];
            }
#pragma unroll
        for (int p = 0; p < 8; p++) {
            int y2 = (p >> 2) & 1, y3 = (p >> 1) & 1, y4 = p & 1;
            int m = y4 ^ y3;
            u64 KR  = pk2(k45r[m][y4], k45r[m][y4 ^ 1]);
            u64 KI  = pk2(k45i[m][y4], k45i[m][y4 ^ 1]);
            u64 NKI = pk2(-k45i[m][y4], -k45i[m][y4 ^ 1]);
            R[p] = f2fma(NKI, CIm[y2][y3], f2mul(KR, CRm[y2][y3]));
            I[p] = f2fma(KI, CRm[y2][y3], f2mul(KR, CIm[y2][y3]));
        }
    }

    // --- layer-1 local gates (q2,q3,q4,q5) ---
    su2_loc<4>(R, I, g_u + 16);
    su2_loc<2>(R, I, g_u + 24);
    su2_loc<1>(R, I, g_u + 32);
    su2_q5(R, I, g_u + 40);

    // --- layer 2 (full) ---
    layer<1>(R, I, g_u + 48, t0, t1);

    // --- layer-3 prefix: C01 relabel -> map q0=t1, q1=t0; C12 SEL (c=t0);
    //     C23, C34 renames. C45, C50 + gates absorbed into observables. ---
    {
        bool c = (t0 != 0);
#pragma unroll
        for (int p = 0; p < 4; p++) {
            u64 a = R[p], b = R[p + 4];
            R[p] = c ? b : a;  R[p + 4] = c ? a : b;
            a = I[p]; b = I[p + 4];
            I[p] = c ? b : a;  I[p + 4] = c ? a : b;
        }
        swp(R, 4, 6); swp(R, 5, 7); swp(I, 4, 6); swp(I, 5, 7);
        swp(R, 2, 3); swp(R, 6, 7); swp(I, 2, 3); swp(I, 6, 7);
    }

    // --- measurements on the pre-C45/C50 state (map: q0=t1, q1=t0) ---
    u64 aS = 0, az2 = 0, az3 = 0, az4 = 0;
    u64 ex2 = 0, ey2 = 0, ex3 = 0, ey3 = 0, x45 = 0, y45 = 0;
    u64 ax0 = 0, zy0 = 0, x50 = 0, zyx = 0, ax1 = 0, ay1 = 0;
#pragma unroll
    for (int p = 0; p < 8; p++) {
        u64 pr = f2fma(I[p], I[p], f2mul(R[p], R[p]));
        aS  = f2add(aS, pr);
        az2 = f2add(az2, (p & 4) ? (pr ^ SGN2) : pr);
        az3 = f2add(az3, (p & 2) ? (pr ^ SGN2) : pr);
        az4 = f2add(az4, (p & 1) ? (pr ^ SGN2) : pr);
        if (!(p & 4)) {
            ex2 = f2fma(R[p], R[p | 4], f2fma(I[p], I[p | 4], ex2));
            ey2 = f2fma(R[p], I[p | 4], f2fma(I[p] ^ SGN2, R[p | 4], ey2));
        }
        if (!(p & 2)) {
            ex3 = f2fma(R[p], R[p | 2], f2fma(I[p], I[p | 2], ex3));
            ey3 = f2fma(R[p], I[p | 2], f2fma(I[p] ^ SGN2, R[p | 2], ey3));
        }
        x45 = f2fma(R[p], f2swap(R[p ^ 1]), f2fma(I[p], f2swap(I[p ^ 1]), x45));
        if (!(p & 1)) {
            y45 = f2fma(R[p], f2swap(I[p | 1]),
                        f2fma(I[p] ^ SGN2, f2swap(R[p | 1]), y45));
        }
        // q0 round: partner flips logical q0 (= t1) only -> lane xor 2
        u64 PR = __shfl_xor_sync(0xffffffffu, R[p], 2);
        u64 PI = __shfl_xor_sync(0xffffffffu, I[p], 2);
        ax0 = f2fma(R[p], PR, f2fma(I[p], PI, ax0));
        {
            u64 v = f2fma(R[p], PI, f2mul(I[p] ^ SGN2, PR));
            zy0 = f2add(zy0, (p & 1) ? (v ^ SGN2) : v);
        }
        x50 = f2fma(R[p], f2swap(PR), f2fma(I[p], f2swap(PI), x50));
        {
            u64 v = f2fma(R[p], f2swap(PI), f2mul(I[p] ^ SGN2, f2swap(PR)));
            zyx = f2add(zyx, (p & 1) ? (v ^ SGN2) : v);
        }
        // q1 round: partner flips logical q1 (= t0) only -> lane xor 1
        u64 QR = __shfl_xor_sync(0xffffffffu, R[p], 1);
        u64 QI = __shfl_xor_sync(0xffffffffu, I[p], 1);
        ax1 = f2fma(R[p], QR, f2fma(I[p], QI, ax1));
        ay1 = f2fma(R[p], QI, f2fma(I[p] ^ SGN2, QR, ay1));
    }

    float lo, hi;
    upk2(aS,  lo, hi); float sAll = lo + hi;
    upk2(az2, lo, hi); float sZ2  = lo + hi;
    upk2(az3, lo, hi); float sZ3  = lo + hi;
    upk2(az4, lo, hi); float sZ4  = lo + hi, sZ45 = lo - hi;
    upk2(ex2, lo, hi); float sEx2 = lo + hi;
    upk2(ey2, lo, hi); float sEy2 = lo + hi;
    upk2(ex3, lo, hi); float sEx3 = lo + hi;
    upk2(ey3, lo, hi); float sEy3 = lo + hi;
    upk2(x45, lo, hi); float sX45 = lo + hi;
    upk2(y45, lo, hi); float sY45 = lo + hi;
    upk2(ax0, lo, hi); float sX0  = lo + hi;
    upk2(zy0, lo, hi); float sZY0 = lo - hi;
    upk2(x50, lo, hi); float sX50 = lo + hi;
    upk2(zyx, lo, hi); float sZYX = lo - hi;
    upk2(ax1, lo, hi); float sX1  = lo + hi;
    upk2(ay1, lo, hi); float sY1  = lo + hi;

    float sgT = t1 ? -1.0f : 1.0f;        // q0 role sign (q0 = t1)
    float sg1 = t0 ? -1.0f : 1.0f;        // q1 role sign (q1 = t0)

    float m0 = g_m[2]  * (sgT * sZ45) + g_m[0]  * sX0  + g_m[1]  * (sgT * sZY0);
    float m1 = g_m[6]  * (sg1 * sAll) + g_m[4]  * sX1  + g_m[5]  * (sg1 * sY1);
    float m2 = g_m[10] * sZ2          + g_m[8]  * sEx2 + g_m[9]  * sEy2;
    float m3 = g_m[14] * sZ3          + g_m[12] * sEx3 + g_m[13] * sEy3;
    float m4 = g_m[18] * sZ4          + g_m[16] * sX45 + g_m[17] * sY45;
    float m5 = g_m[22] * sZ45         + g_m[20] * sX50 + g_m[21] * sZYX;

    // reduce across the 4-thread group
    m0 += __shfl_xor_sync(0xffffffffu, m0, 1); m0 += __shfl_xor_sync(0xffffffffu, m0, 2);
    m1 += __shfl_xor_sync(0xffffffffu, m1, 1); m1 += __shfl_xor_sync(0xffffffffu, m1, 2);
    m2 += __shfl_xor_sync(0xffffffffu, m2, 1); m2 += __shfl_xor_sync(0xffffffffu, m2, 2);
    m3 += __shfl_xor_sync(0xffffffffu, m3, 1); m3 += __shfl_xor_sync(0xffffffffu, m3, 2);
    m4 += __shfl_xor_sync(0xffffffffu, m4, 1); m4 += __shfl_xor_sync(0xffffffffu, m4, 2);
    m5 += __shfl_xor_sync(0xffffffffu, m5, 1); m5 += __shfl_xor_sync(0xffffffffu, m5, 2);

    if (t == 0) {
        float4* o4 = reinterpret_cast<float4*>(out) + (long)st * 2;
        o4[0] = make_float4(m0, m1, m2, m3);
        o4[1] = make_float4(m4, m5, m0, m1);
    }
}

extern "C" void kernel_launch(void* const* d_in, const int* in_sizes, int n_in,
                              void* d_out, int out_size) {
    const float* x     = (const float*)d_in[0];
    const float* theta = (const float*)d_in[1];
    float* out = (float*)d_out;
    int Bn = in_sizes[0] / 24;

    prep_kernel<<<1, 32>>>(theta);
    long threads = 4L * Bn;
    int blocks = (int)((threads + 127) / 128);
    qsim_kernel<<<blocks, 128>>>(x, out, Bn);
}

// round 12
// speedup vs baseline: 2.3345x; 1.0070x over previous
#include <cuda_runtime.h>

// ---------------------------------------------------------------------------
// 6-qubit, 3-layer circuit, B=131072. FOUR threads per state (t1,t0 thread
// bits), each holding 8 packed-f32x2 real + 8 imag regs (lane = q5; pack bits
// 2..0 = q2,q3,q4).
//  * Layer-1 CNOT ring + its q0,q1 gates: absorbed ANALYTICALLY into the
//    initial build. ring(product) amplitude:
//      amp(y) = u0[y0^y5] u1[y0^y1^y5] u2[y1^y2] u3[y2^y3] u4[y3^y4] u5[y4^y5]
//    and U0 (y0=t1), U1 (y1=t0) applied via per-thread scalar contraction.
//  * Layer-1 q2..q5 gates: local packed butterflies (no shfl).
//  * Layer 2: full layer with C01 relabel (S=1), C12 SELs, C23/C34 renames,
//    C45+C50 folded into the q0-gate gather.
//  * Layer 3: C01 relabel (map -> q0=t1, q1=t0), C12 SEL (c=t0), C23/C34
//    renames; C45, C50 and all six gates absorbed into observables:
//      O~0 = nx X0 + ny Z4Z5Y0 + nz Z4Z5Z0 ; O~1 = nx X1 + ny Y1 + nz Z1
//      O~2,O~3 plain ; O~4 = nx X4X5 + ny Y4X5 + nz Z4
//      O~5 = nx X5X0 + ny Z4Y5X0 + nz Z4Z5
//    Measurement q0-partner = lane xor 2; q1-partner = xor 1.
// ---------------------------------------------------------------------------

typedef unsigned long long u64;
#define SGN2 0x8000000080000000ULL

__device__ __forceinline__ u64 pk2(float a, float b) {
    u64 r; asm("mov.b64 %0,{%1,%2};" : "=l"(r) : "f"(a), "f"(b)); return r;
}
__device__ __forceinline__ void upk2(u64 v, float& a, float& b) {
    asm("mov.b64 {%0,%1},%2;" : "=f"(a), "=f"(b) : "l"(v));
}
__device__ __forceinline__ u64 bc2(float a) { return pk2(a, a); }
__device__ __forceinline__ u64 f2mul(u64 a, u64 b) {
    u64 d; asm("mul.rn.f32x2 %0,%1,%2;" : "=l"(d) : "l"(a), "l"(b)); return d;
}
__device__ __forceinline__ u64 f2fma(u64 a, u64 b, u64 c) {
    u64 d; asm("fma.rn.f32x2 %0,%1,%2,%3;" : "=l"(d) : "l"(a), "l"(b), "l"(c)); return d;
}
__device__ __forceinline__ u64 f2add(u64 a, u64 b) {
    u64 d; asm("add.rn.f32x2 %0,%1,%2;" : "=l"(d) : "l"(a), "l"(b)); return d;
}
__device__ __forceinline__ u64 f2swap(u64 a) {
    u64 d;
    asm("{\n\t.reg .b32 x,y;\n\tmov.b64 {x,y},%1;\n\tmov.b64 %0,{y,x};\n\t}"
        : "=l"(d) : "l"(a));
    return d;
}

// Broadcast tables: layer0 slots 16..45 (q2..q5 only), layer1 full 48.
__device__ u64 g_u[2 * 48];
// Layer-1 q0,q1 raw SU(2) coefficients: [a0r,a0i,b0r,b0i, a1r,a1i,b1r,b1i]
__device__ float g_l1[8];
// Observable combine constants per qubit: [cx, cy, cz, 0]
__device__ float g_m[6 * 4];

__global__ void prep_kernel(const float* __restrict__ theta) {
    int t = threadIdx.x;
    if (t < 18) {
        int l = t / 6, q = t % 6;
        const float* th = theta + t * 3;
        float sx, cx, sy, cy, sz, cz;
        __sincosf(th[0] * 0.5f, &sx, &cx);
        __sincosf(th[1] * 0.5f, &sy, &cy);
        __sincosf(th[2] * 0.5f, &sz, &cz);
        float m00r =  cy * cx, m00i =  sy * sx;
        float m01r = -sy * cx, m01i = -cy * sx;
        float ar = cz * m00r + sz * m00i, ai = cz * m00i - sz * m00r;
        float br = cz * m01r + sz * m01i, bi = cz * m01i - sz * m01r;
        if (l < 2) {
            u64* g = g_u + l * 48;
            if (q == 0) {
                if (l == 0) {
                    g_l1[0] = ar; g_l1[1] = ai; g_l1[2] = br; g_l1[3] = bi;
                } else {
                    g[0] = bc2(ar); g[1] = bc2(ai); g[2] = bc2(br);
                    g[3] = bc2(bi); g[4] = bc2(-bi);
                }
            } else if (q == 1) {
                if (l == 0) {
                    g_l1[4] = ar; g_l1[5] = ai; g_l1[6] = br; g_l1[7] = bi;
                } else {
                    g[8] = bc2(ar); g[9] = bc2(ai); g[10] = bc2(br); g[11] = bc2(bi);
                }
            } else if (q < 5) {
                u64* h = g + 16 + (q - 2) * 8;
                h[0] = bc2(ar); h[1] = bc2(ai); h[2] = bc2(-ai);
                h[3] = bc2(br); h[4] = bc2(-br); h[5] = bc2(bi); h[6] = bc2(-bi);
            } else {
                u64* h = g + 40;
                h[0] = pk2(ar, ar);   h[1] = pk2(-ai, ai);
                h[2] = pk2(br, -br);  h[3] = pk2(-bi, -bi);
                h[4] = pk2(ai, -ai);  h[5] = pk2(bi, bi);
            }
        } else {
            // layer 3: observable n-vector. even q: U†ZU, odd q: U†XU
            float nx, ny, nz;
            if ((q & 1) == 0) {
                nz = (ar * ar + ai * ai) - (br * br + bi * bi);
                nx = 2.0f * (br * ar + bi * ai);
                ny = 2.0f * (br * ai - bi * ar);
            } else {
                nz = -2.0f * (ar * br - ai * bi);
                nx = ar * ar - ai * ai - br * br + bi * bi;
                ny = 2.0f * (ar * ai + br * bi);
            }
            if (q == 2 || q == 3) { nx *= 2.0f; ny *= 2.0f; }
            if (q == 4) { ny *= 2.0f; }
            g_m[q * 4 + 0] = nx;
            g_m[q * 4 + 1] = ny;
            g_m[q * 4 + 2] = nz;
        }
    }
}

// Local SU(2) on a pack bit (MP = 4 -> q2, 2 -> q3, 1 -> q4).
template <int MP>
__device__ __forceinline__ void su2_loc(u64* R, u64* I, const u64* __restrict__ u) {
    u64 ar = u[0], ai = u[1], nai = u[2];
    u64 br = u[3], nbr = u[4], bi = u[5], nbi = u[6];
#pragma unroll
    for (int g = 0; g < 4; g++) {
        int p0 = (g & (MP - 1)) | ((g & ~(MP - 1)) << 1);
        int p1 = p0 | MP;
        u64 Ar = R[p0], Ai = I[p0], Br = R[p1], Bi = I[p1];
        R[p0] = f2fma(nbi, Bi, f2fma(br, Br, f2fma(nai, Ai, f2mul(ar, Ar))));
        I[p0] = f2fma(br, Bi, f2fma(bi, Br, f2fma(ai, Ar, f2mul(ar, Ai))));
        R[p1] = f2fma(ai, Bi, f2fma(ar, Br, f2fma(nbi, Ai, f2mul(nbr, Ar))));
        I[p1] = f2fma(nai, Br, f2fma(ar, Bi, f2fma(bi, Ar, f2mul(nbr, Ai))));
    }
}

// Local SU(2) on qubit 5 (lane), within-pack butterfly via half-swap.
__device__ __forceinline__ void su2_q5(u64* R, u64* I, const u64* __restrict__ u) {
    u64 aa = u[0], am = u[1], bp = u[2], nb2 = u[3], ap = u[4], bb = u[5];
#pragma unroll
    for (int p = 0; p < 8; p++) {
        u64 r = R[p], m = I[p];
        u64 sr = f2swap(r), sm = f2swap(m);
        R[p] = f2fma(nb2, sm, f2fma(bp, sr, f2fma(am, m, f2mul(aa, r))));
        I[p] = f2fma(bb, sr, f2fma(bp, sm, f2fma(ap, r, f2mul(aa, m))));
    }
}

__device__ __forceinline__ void swp(u64* A, int i, int j) {
    u64 t = A[i]; A[i] = A[j]; A[j] = t;
}

// Full layer (used for layer 2). S=1 mapping AFTER C01 relabel: q0=t1, q1=t0^t1.
template <int S>
__device__ __forceinline__ void layer(u64* R, u64* I, const u64* __restrict__ cf,
                                      int t0, int t1) {
    int q1log = S ? (t0 ^ t1) : t0;
    bool c = (q1log != 0);
#pragma unroll
    for (int p = 0; p < 4; p++) {
        u64 a = R[p], b = R[p + 4];
        R[p] = c ? b : a;  R[p + 4] = c ? a : b;
        a = I[p]; b = I[p + 4];
        I[p] = c ? b : a;  I[p + 4] = c ? a : b;
    }
    swp(R, 4, 6); swp(R, 5, 7); swp(I, 4, 6); swp(I, 5, 7);
    swp(R, 2, 3); swp(R, 6, 7); swp(I, 2, 3); swp(I, 6, 7);

    // q0 gate (cross-thread), CNOT(4,5) + CNOT(5,0) folded into the gather.
    {
        u64 smask = t1 ? SGN2 : 0ULL;
        u64 car  = cf[0];
        u64 cai  = cf[1] ^ smask;
        u64 ncai = cai ^ SGN2;
        u64 cbr  = cf[2] ^ smask;
        u64 cbi  = cf[3];
        u64 ncbi = cf[4];
        constexpr int PX = S ? 3 : 2;
#pragma unroll
        for (int p = 0; p < 8; p++) {
            u64 LR = R[p], LI = I[p];
            u64 MR = __shfl_xor_sync(0xffffffffu, LR, PX);
            u64 MI = __shfl_xor_sync(0xffffffffu, LI, PX);
            float lr0, lr1, li0, li1, mr0, mr1, mi0, mi1;
            upk2(LR, lr0, lr1); upk2(LI, li0, li1);
            upk2(MR, mr0, mr1); upk2(MI, mi0, mi1);
            u64 AR, AI, BR, BI;
            if ((p & 1) == 0) {
                AR = pk2(lr0, mr1); AI = pk2(li0, mi1);
                BR = pk2(mr0, lr1); BI = pk2(mi0, li1);
            } else {
                AR = pk2(lr1, mr0); AI = pk2(li1, mi0);
                BR = pk2(mr1, lr0); BI = pk2(mi1, li0);
            }
            R[p] = f2fma(ncbi, BI, f2fma(cbr, BR, f2fma(ncai, AI, f2mul(car, AR))));
            I[p] = f2fma(cbi, BR, f2fma(cbr, BI, f2fma(cai, AR, f2mul(car, AI))));
        }
    }

    // q1 gate (cross-thread, partner xor 1, role = q1log)
    {
        u64 m1   = q1log ? SGN2 : 0ULL;
        u64 ar   = cf[8];
        u64 cai  = cf[9] ^ m1;
        u64 ncai = cai ^ SGN2;
        u64 cbr  = cf[10] ^ m1;
        u64 bi   = cf[11];
        u64 nbi  = bi ^ SGN2;
#pragma unroll
        for (int p = 0; p < 8; p++) {
            u64 LR = R[p], LI = I[p];
            u64 MR = __shfl_xor_sync(0xffffffffu, LR, 1);
            u64 MI = __shfl_xor_sync(0xffffffffu, LI, 1);
            R[p] = f2fma(nbi, MI, f2fma(cbr, MR, f2fma(ncai, LI, f2mul(ar, LR))));
            I[p] = f2fma(bi, MR, f2fma(cbr, MI, f2fma(cai, LR, f2mul(ar, LI))));
        }
    }

    su2_loc<4>(R, I, cf + 16);
    su2_loc<2>(R, I, cf + 24);
    su2_loc<1>(R, I, cf + 32);
    su2_q5(R, I, cf + 40);
}

__global__ __launch_bounds__(128, 6) void qsim_kernel(
    const float* __restrict__ x, float* __restrict__ out, int Bn)
{
    int gid = blockIdx.x * 128 + threadIdx.x;
    int st = gid >> 2;
    if (st >= Bn) return;
    int t = gid & 3;
    int t0 = t & 1, t1 = (t >> 1) & 1;

    // --- encoding (1 sincos per qubit; double-angle for a/2 terms) ---
    const float4* x4 = reinterpret_cast<const float4*>(x) + (long)st * 6;
    float ur[6][2], ui[6][2];
#pragma unroll
    for (int q = 0; q < 6; q++) {
        float4 v = __ldg(&x4[q]);
        float a = (v.x + v.y + v.z + v.w) * 0.25f;
        a = fminf(6.0f, fmaxf(-6.0f, a)) * (3.14159265358979323846f / 6.0f);
        float s4, c4;
        __sincosf(a * 0.25f, &s4, &c4);
        float s2 = 2.0f * s4 * c4;
        float c2 = fmaf(-2.0f * s4, s4, 1.0f);
        ur[q][0] = c2 * c4;  ui[q][0] = -c2 * s4;
        ur[q][1] = s2 * s4;  ui[q][1] = -s2 * c4;
    }

    // --- build: ring1(product) with U0 (on y0=t1) and U1 (on y1=t0) absorbed.
    //     amp(y) = sum_{c0,c1} U0[t1,c0] U1[t0,c1] u0[c0^y5] u1[c0^c1^y5]
    //              u2[c1^y2] u3[y2^y3] u4[y3^y4] u5[y4^y5]
    float C0r, C0i, C1r, C1i, D0r, D0i, D1r, D1i;
    {
        float a0r = g_l1[0], a0i = g_l1[1], b0r = g_l1[2], b0i = g_l1[3];
        C0r = t1 ? -b0r : a0r;  C0i = t1 ?  b0i : a0i;
        C1r = t1 ?  a0r : b0r;  C1i = t1 ? -a0i : b0i;
        float a1r = g_l1[4], a1i = g_l1[5], b1r = g_l1[6], b1i = g_l1[7];
        D0r = t0 ? -b1r : a1r;  D0i = t0 ?  b1i : a1i;
        D1r = t0 ?  a1r : b1r;  D1i = t0 ? -a1i : b1i;
    }
    float Vr[2][2], Vi[2][2];  // [y2][y5]
    {
        float Tr[2][2], Ti[2][2];  // [c0][y5]
#pragma unroll
        for (int y5 = 0; y5 < 2; y5++) {
            Tr[0][y5] = C0r * ur[0][y5] - C0i * ui[0][y5];
            Ti[0][y5] = C0r * ui[0][y5] + C0i * ur[0][y5];
            Tr[1][y5] = C1r * ur[0][1 ^ y5] - C1i * ui[0][1 ^ y5];
            Ti[1][y5] = C1r * ui[0][1 ^ y5] + C1i * ur[0][1 ^ y5];
        }
        float Wr[2][2], Wi[2][2];  // [c1][y5]
#pragma unroll
        for (int c1 = 0; c1 < 2; c1++)
#pragma unroll
            for (int y5 = 0; y5 < 2; y5++) {
                int j = c1 ^ y5;
                Wr[c1][y5] = Tr[0][y5] * ur[1][j] - Ti[0][y5] * ui[1][j]
                           + Tr[1][y5] * ur[1][j ^ 1] - Ti[1][y5] * ui[1][j ^ 1];
                Wi[c1][y5] = Tr[0][y5] * ui[1][j] + Ti[0][y5] * ur[1][j]
                           + Tr[1][y5] * ui[1][j ^ 1] + Ti[1][y5] * ur[1][j ^ 1];
            }
        float Pr[2][2], Pi2[2][2];  // T2 [c1][y5]
#pragma unroll
        for (int y5 = 0; y5 < 2; y5++) {
            Pr[0][y5]  = D0r * Wr[0][y5] - D0i * Wi[0][y5];
            Pi2[0][y5] = D0r * Wi[0][y5] + D0i * Wr[0][y5];
            Pr[1][y5]  = D1r * Wr[1][y5] - D1i * Wi[1][y5];
            Pi2[1][y5] = D1r * Wi[1][y5] + D1i * Wr[1][y5];
        }
#pragma unroll
        for (int y2 = 0; y2 < 2; y2++)
#pragma unroll
            for (int y5 = 0; y5 < 2; y5++) {
                Vr[y2][y5] = Pr[0][y5] * ur[2][y2] - Pi2[0][y5] * ui[2][y2]
                           + Pr[1][y5] * ur[2][y2 ^ 1] - Pi2[1][y5] * ui[2][y2 ^ 1];
                Vi[y2][y5] = Pr[0][y5] * ui[2][y2] + Pi2[0][y5] * ur[2][y2]
                           + Pr[1][y5] * ui[2][y2 ^ 1] + Pi2[1][y5] * ur[2][y2 ^ 1];
            }
    }
    // packed over lane y5, expand y3 (pack bit1) via u3[y2^y3]
    u64 CRm[2][2], CIm[2][2];  // [y2][y3]
    {
        u64 BR[2], BI[2];
        BR[0] = pk2(Vr[0][0], Vr[0][1]); BI[0] = pk2(Vi[0][0], Vi[0][1]);
        BR[1] = pk2(Vr[1][0], Vr[1][1]); BI[1] = pk2(Vi[1][0], Vi[1][1]);
        u64 w3r[2], w3i[2], n3i[2];
        w3r[0] = bc2(ur[3][0]); w3i[0] = bc2(ui[3][0]); n3i[0] = bc2(-ui[3][0]);
        w3r[1] = bc2(ur[3][1]); w3i[1] = bc2(ui[3][1]); n3i[1] = bc2(-ui[3][1]);
#pragma unroll
        for (int y2 = 0; y2 < 2; y2++)
#pragma unroll
            for (int y3 = 0; y3 < 2; y3++) {
                int m = y2 ^ y3;
                CRm[y2][y3] = f2fma(n3i[m], BI[y2], f2mul(w3r[m], BR[y2]));
                CIm[y2][y3] = f2fma(w3i[m], BR[y2], f2mul(w3r[m], BI[y2]));
            }
    }
    // K[y3][y4] = packed (u4[y4^y3]*u5[y4], u4[y4^y3]*u5[1^y4]); expand y4
    u64 R[8], I[8];
    {
        float k45r[2][2], k45i[2][2];  // [m][n] = u4[m]*u5[n]
#pragma unroll
        for (int m = 0; m < 2; m++)
#pragma unroll
            for (int n = 0; n < 2; n++) {
                k45r[m][n] = ur[4][m] * ur[5][n] - ui[4][m] * ui[5][n];
                k45i[m][n] = ur[4][m] * ui[5][n] + ui[4][m] * ur[5][n];
            }
#pragma unroll
        for (int p = 0; p < 8; p++) {
            int y2 = (p >> 2) & 1, y3 = (p >> 1) & 1, y4 = p & 1;
            int m = y4 ^ y3;
            u64 KR  = pk2(k45r[m][y4], k45r[m][y4 ^ 1]);
            u64 KI  = pk2(k45i[m][y4], k45i[m][y4 ^ 1]);
            u64 NKI = pk2(-k45i[m][y4], -k45i[m][y4 ^ 1]);
            R[p] = f2fma(NKI, CIm[y2][y3], f2mul(KR, CRm[y2][y3]));
            I[p] = f2fma(KI, CRm[y2][y3], f2mul(KR, CIm[y2][y3]));
        }
    }

    // --- layer-1 local gates (q2,q3,q4,q5) ---
    su2_loc<4>(R, I, g_u + 16);
    su2_loc<2>(R, I, g_u + 24);
    su2_loc<1>(R, I, g_u + 32);
    su2_q5(R, I, g_u + 40);

    // --- layer 2 (full) ---
    layer<1>(R, I, g_u + 48, t0, t1);

    // --- layer-3 prefix: C01 relabel -> map q0=t1, q1=t0; C12 SEL (c=t0);
    //     C23, C34 renames. C45, C50 + gates absorbed into observables. ---
    {
        bool c = (t0 != 0);
#pragma unroll
        for (int p = 0; p < 4; p++) {
            u64 a = R[p], b = R[p + 4];
            R[p] = c ? b : a;  R[p + 4] = c ? a : b;
            a = I[p]; b = I[p + 4];
            I[p] = c ? b : a;  I[p + 4] = c ? a : b;
        }
        swp(R, 4, 6); swp(R, 5, 7); swp(I, 4, 6); swp(I, 5, 7);
        swp(R, 2, 3); swp(R, 6, 7); swp(I, 2, 3); swp(I, 6, 7);
    }

    // --- measurements on the pre-C45/C50 state (map: q0=t1, q1=t0) ---
    u64 aS = 0, az2 = 0, az3 = 0, az4 = 0;
    u64 ex2 = 0, ey2 = 0, ex3 = 0, ey3 = 0, x45 = 0, y45 = 0;
    u64 ax0 = 0, zy0 = 0, x50 = 0, zyx = 0, ax1 = 0, ay1 = 0;
#pragma unroll
    for (int p = 0; p < 8; p++) {
        u64 pr = f2fma(I[p], I[p], f2mul(R[p], R[p]));
        aS  = f2add(aS, pr);
        az2 = f2add(az2, (p & 4) ? (pr ^ SGN2) : pr);
        az3 = f2add(az3, (p & 2) ? (pr ^ SGN2) : pr);
        az4 = f2add(az4, (p & 1) ? (pr ^ SGN2) : pr);
        if (!(p & 4)) {
            ex2 = f2fma(R[p], R[p | 4], f2fma(I[p], I[p | 4], ex2));
            ey2 = f2fma(R[p], I[p | 4], f2fma(I[p] ^ SGN2, R[p | 4], ey2));
        }
        if (!(p & 2)) {
            ex3 = f2fma(R[p], R[p | 2], f2fma(I[p], I[p | 2], ex3));
            ey3 = f2fma(R[p], I[p | 2], f2fma(I[p] ^ SGN2, R[p | 2], ey3));
        }
        x45 = f2fma(R[p], f2swap(R[p ^ 1]), f2fma(I[p], f2swap(I[p ^ 1]), x45));
        if (!(p & 1)) {
            y45 = f2fma(R[p], f2swap(I[p | 1]),
                        f2fma(I[p] ^ SGN2, f2swap(R[p | 1]), y45));
        }
        // q0 round: partner flips logical q0 (= t1) only -> lane xor 2
        u64 PR = __shfl_xor_sync(0xffffffffu, R[p], 2);
        u64 PI = __shfl_xor_sync(0xffffffffu, I[p], 2);
        ax0 = f2fma(R[p], PR, f2fma(I[p], PI, ax0));
        {
            u64 v = f2fma(R[p], PI, f2mul(I[p] ^ SGN2, PR));
            zy0 = f2add(zy0, (p & 1) ? (v ^ SGN2) : v);
        }
        x50 = f2fma(R[p], f2swap(PR), f2fma(I[p], f2swap(PI), x50));
        {
            u64 v = f2fma(R[p], f2swap(PI), f2mul(I[p] ^ SGN2, f2swap(PR)));
            zyx = f2add(zyx, (p & 1) ? (v ^ SGN2) : v);
        }
        // q1 round: partner flips logical q1 (= t0) only -> lane xor 1
        u64 QR = __shfl_xor_sync(0xffffffffu, R[p], 1);
        u64 QI = __shfl_xor_sync(0xffffffffu, I[p], 1);
        ax1 = f2fma(R[p], QR, f2fma(I[p], QI, ax1));
        ay1 = f2fma(R[p], QI, f2fma(I[p] ^ SGN2, QR, ay1));
    }

    float lo, hi;
    upk2(aS,  lo, hi); float sAll = lo + hi;
    upk2(az2, lo, hi); float sZ2  = lo + hi;
    upk2(az3, lo, hi); float sZ3  = lo + hi;
    upk2(az4, lo, hi); float sZ4  = lo + hi, sZ45 = lo - hi;
    upk2(ex2, lo, hi); float sEx2 = lo + hi;
    upk2(ey2, lo, hi); float sEy2 = lo + hi;
    upk2(ex3, lo, hi); float sEx3 = lo + hi;
    upk2(ey3, lo, hi); float sEy3 = lo + hi;
    upk2(x45, lo, hi); float sX45 = lo + hi;
    upk2(y45, lo, hi); float sY45 = lo + hi;
    upk2(ax0, lo, hi); float sX0  = lo + hi;
    upk2(zy0, lo, hi); float sZY0 = lo - hi;
    upk2(x50, lo, hi); float sX50 = lo + hi;
    upk2(zyx, lo, hi); float sZYX = lo - hi;
    upk2(ax1, lo, hi); float sX1  = lo + hi;
    upk2(ay1, lo, hi); float sY1  = lo + hi;

    float sgT = t1 ? -1.0f : 1.0f;        // q0 role sign (q0 = t1)
    float sg1 = t0 ? -1.0f : 1.0f;        // q1 role sign (q1 = t0)

    float m0 = g_m[2]  * (sgT * sZ45) + g_m[0]  * sX0  + g_m[1]  * (sgT * sZY0);
    float m1 = g_m[6]  * (sg1 * sAll) + g_m[4]  * sX1  + g_m[5]  * (sg1 * sY1);
    float m2 = g_m[10] * sZ2          + g_m[8]  * sEx2 + g_m[9]  * sEy2;
    float m3 = g_m[14] * sZ3          + g_m[12] * sEx3 + g_m[13] * sEy3;
    float m4 = g_m[18] * sZ4          + g_m[16] * sX45 + g_m[17] * sY45;
    float m5 = g_m[22] * sZ45         + g_m[20] * sX50 + g_m[21] * sZYX;

    // reduce across the 4-thread group
    m0 += __shfl_xor_sync(0xffffffffu, m0, 1); m0 += __shfl_xor_sync(0xffffffffu, m0, 2);
    m1 += __shfl_xor_sync(0xffffffffu, m1, 1); m1 += __shfl_xor_sync(0xffffffffu, m1, 2);
    m2 += __shfl_xor_sync(0xffffffffu, m2, 1); m2 += __shfl_xor_sync(0xffffffffu, m2, 2);
    m3 += __shfl_xor_sync(0xffffffffu, m3, 1); m3 += __shfl_xor_sync(0xffffffffu, m3, 2);
    m4 += __shfl_xor_sync(0xffffffffu, m4, 1); m4 += __shfl_xor_sync(0xffffffffu, m4, 2);
    m5 += __shfl_xor_sync(0xffffffffu, m5, 1); m5 += __shfl_xor_sync(0xffffffffu, m5, 2);

    if (t == 0) {
        float4* o4 = reinterpret_cast<float4*>(out) + (long)st * 2;
        o4[0] = make_float4(m0, m1, m2, m3);
        o4[1] = make_float4(m4, m5, m0, m1);
    }
}

extern "C" void kernel_launch(void* const* d_in, const int* in_sizes, int n_in,
                              void* d_out, int out_size) {
    const float* x     = (const float*)d_in[0];
    const float* theta = (const float*)d_in[1];
    float* out = (float*)d_out;
    int Bn = in_sizes[0] / 24;

    prep_kernel<<<1, 32>>>(theta);
    long threads = 4L * Bn;
    int blocks = (int)((threads + 127) / 128);
    qsim_kernel<<<blocks, 128>>>(x, out, Bn);
}

// round 13
// speedup vs baseline: 2.4599x; 1.0537x over previous
#include <cuda_runtime.h>

// ---------------------------------------------------------------------------
// 6-qubit, 3-layer circuit, B=131072. TWO threads per state (t = q0), each
// holding 16 packed-f32x2 real + 16 imag regs (lane = q5; pack bits
// 3..0 = q1,q2,q3,q4).
//  * Layer-1 CNOT ring + its q0,q1 gates absorbed analytically into build:
//      amp(y) = sum_{c0,c1} U0[t,c0] U1[y1,c1] u0[c0^y5] u1[c0^c1^y5]
//               u2[c1^y2] u3[y2^y3] u4[y3^y4] u5[y4^y5]
//  * Layer-1 q2..q5 gates: local packed butterflies.
//  * Layer 2: C01 = t-predicated SELs (target bit3); C12/C23/C34 renames;
//    C45+C50 folded into the cross-thread q0-gate gather (partner xor 1);
//    q1..q5 local butterflies.
//  * Layer 3: C01 SELs + C12/C23/C34 renames; C45, C50 and all six gates
//    absorbed into observables (Heisenberg):
//      O~0 = nx X0 + ny Z4Z5Y0 + nz Z4Z5Z0 ; O~1 = nx X1 + ny Y1 + nz Z1
//      O~2,O~3 plain ; O~4 = nx X4X5 + ny Y4X5 + nz Z4
//      O~5 = nx X5X0 + ny Z4Y5X0 + nz Z4Z5
//    q0-observable partner = lane xor 1; q1 observables pack-local (bit3).
// ---------------------------------------------------------------------------

typedef unsigned long long u64;
#define SGN2 0x8000000080000000ULL

__device__ __forceinline__ u64 pk2(float a, float b) {
    u64 r; asm("mov.b64 %0,{%1,%2};" : "=l"(r) : "f"(a), "f"(b)); return r;
}
__device__ __forceinline__ void upk2(u64 v, float& a, float& b) {
    asm("mov.b64 {%0,%1},%2;" : "=f"(a), "=f"(b) : "l"(v));
}
__device__ __forceinline__ u64 bc2(float a) { return pk2(a, a); }
__device__ __forceinline__ u64 f2mul(u64 a, u64 b) {
    u64 d; asm("mul.rn.f32x2 %0,%1,%2;" : "=l"(d) : "l"(a), "l"(b)); return d;
}
__device__ __forceinline__ u64 f2fma(u64 a, u64 b, u64 c) {
    u64 d; asm("fma.rn.f32x2 %0,%1,%2,%3;" : "=l"(d) : "l"(a), "l"(b), "l"(c)); return d;
}
__device__ __forceinline__ u64 f2add(u64 a, u64 b) {
    u64 d; asm("add.rn.f32x2 %0,%1,%2;" : "=l"(d) : "l"(a), "l"(b)); return d;
}
__device__ __forceinline__ u64 f2swap(u64 a) {
    u64 d;
    asm("{\n\t.reg .b32 x,y;\n\tmov.b64 {x,y},%1;\n\tmov.b64 %0,{y,x};\n\t}"
        : "=l"(d) : "l"(a));
    return d;
}

// g_u[0..47]: layer-1 table (q2..q5 at slots 16..45).
// g_u[48..95]: layer-2 table: q0 at +0 [ar,ai,br,bi,-bi]; q1 at +8 and
//   q2..q4 at +16/+24/+32 [ar,ai,-ai,br,-br,bi,-bi]; q5 at +40.
__device__ u64 g_u[2 * 48];
// Layer-1 q0,q1 raw SU(2) coefficients
__device__ float g_l1[8];
// Observable combine constants per qubit: [cx, cy, cz, pad]
__device__ float g_m[24];

__global__ void prep_kernel(const float* __restrict__ theta) {
    int t = threadIdx.x;
    if (t < 18) {
        int l = t / 6, q = t % 6;
        const float* th = theta + t * 3;
        float sx, cx, sy, cy, sz, cz;
        __sincosf(th[0] * 0.5f, &sx, &cx);
        __sincosf(th[1] * 0.5f, &sy, &cy);
        __sincosf(th[2] * 0.5f, &sz, &cz);
        float m00r =  cy * cx, m00i =  sy * sx;
        float m01r = -sy * cx, m01i = -cy * sx;
        float ar = cz * m00r + sz * m00i, ai = cz * m00i - sz * m00r;
        float br = cz * m01r + sz * m01i, bi = cz * m01i - sz * m01r;
        if (l < 2) {
            u64* g = g_u + l * 48;
            if (q == 0) {
                if (l == 0) {
                    g_l1[0] = ar; g_l1[1] = ai; g_l1[2] = br; g_l1[3] = bi;
                } else {
                    g[0] = bc2(ar); g[1] = bc2(ai); g[2] = bc2(br);
                    g[3] = bc2(bi); g[4] = bc2(-bi);
                }
            } else if (q == 1) {
                if (l == 0) {
                    g_l1[4] = ar; g_l1[5] = ai; g_l1[6] = br; g_l1[7] = bi;
                } else {
                    u64* h = g + 8;
                    h[0] = bc2(ar); h[1] = bc2(ai); h[2] = bc2(-ai);
                    h[3] = bc2(br); h[4] = bc2(-br); h[5] = bc2(bi); h[6] = bc2(-bi);
                }
            } else if (q < 5) {
                u64* h = g + 16 + (q - 2) * 8;
                h[0] = bc2(ar); h[1] = bc2(ai); h[2] = bc2(-ai);
                h[3] = bc2(br); h[4] = bc2(-br); h[5] = bc2(bi); h[6] = bc2(-bi);
            } else {
                u64* h = g + 40;
                h[0] = pk2(ar, ar);   h[1] = pk2(-ai, ai);
                h[2] = pk2(br, -br);  h[3] = pk2(-bi, -bi);
                h[4] = pk2(ai, -ai);  h[5] = pk2(bi, bi);
            }
        } else {
            // layer 3 observable n-vector. even q: U†ZU, odd q: U†XU
            float nx, ny, nz;
            if ((q & 1) == 0) {
                nz = (ar * ar + ai * ai) - (br * br + bi * bi);
                nx = 2.0f * (br * ar + bi * ai);
                ny = 2.0f * (br * ai - bi * ar);
            } else {
                nz = -2.0f * (ar * br - ai * bi);
                nx = ar * ar - ai * ai - br * br + bi * bi;
                ny = 2.0f * (ar * ai + br * bi);
            }
            // fold 2x for single-sided pack-local cross sums
            if (q == 1 || q == 2 || q == 3) { nx *= 2.0f; ny *= 2.0f; }
            if (q == 4) { ny *= 2.0f; }
            g_m[q * 4 + 0] = nx;
            g_m[q * 4 + 1] = ny;
            g_m[q * 4 + 2] = nz;
        }
    }
}

// Local SU(2) on pack bit (MP = 8 -> q1, 4 -> q2, 2 -> q3, 1 -> q4).
template <int MP>
__device__ __forceinline__ void su2_loc(u64* R, u64* I, const u64* __restrict__ u) {
    u64 ar = u[0], ai = u[1], nai = u[2];
    u64 br = u[3], nbr = u[4], bi = u[5], nbi = u[6];
#pragma unroll
    for (int g = 0; g < 8; g++) {
        int p0 = (g & (MP - 1)) | ((g & ~(MP - 1)) << 1);
        int p1 = p0 | MP;
        u64 Ar = R[p0], Ai = I[p0], Br = R[p1], Bi = I[p1];
        R[p0] = f2fma(nbi, Bi, f2fma(br, Br, f2fma(nai, Ai, f2mul(ar, Ar))));
        I[p0] = f2fma(br, Bi, f2fma(bi, Br, f2fma(ai, Ar, f2mul(ar, Ai))));
        R[p1] = f2fma(ai, Bi, f2fma(ar, Br, f2fma(nbi, Ai, f2mul(nbr, Ar))));
        I[p1] = f2fma(nai, Br, f2fma(ar, Bi, f2fma(bi, Ar, f2mul(nbr, Ai))));
    }
}

// Local SU(2) on qubit 5 (lane), within-pack butterfly via half-swap.
__device__ __forceinline__ void su2_q5(u64* R, u64* I, const u64* __restrict__ u) {
    u64 aa = u[0], am = u[1], bp = u[2], nb2 = u[3], ap = u[4], bb = u[5];
#pragma unroll
    for (int p = 0; p < 16; p++) {
        u64 r = R[p], m = I[p];
        u64 sr = f2swap(r), sm = f2swap(m);
        R[p] = f2fma(nb2, sm, f2fma(bp, sr, f2fma(am, m, f2mul(aa, r))));
        I[p] = f2fma(bb, sr, f2fma(bp, sm, f2fma(ap, r, f2mul(aa, m))));
    }
}

__device__ __forceinline__ void swp(u64* A, int i, int j) {
    u64 t = A[i]; A[i] = A[j]; A[j] = t;
}

// CNOT(1,2),(2,3),(3,4) as register renames on the 16-pack array.
__device__ __forceinline__ void cnot_ring_mid(u64* R, u64* I) {
    // C12: packs with bit3=1 flip bit2
    swp(R, 8, 12); swp(R, 9, 13); swp(R, 10, 14); swp(R, 11, 15);
    swp(I, 8, 12); swp(I, 9, 13); swp(I, 10, 14); swp(I, 11, 15);
    // C23: packs with bit2=1 flip bit1
    swp(R, 4, 6); swp(R, 5, 7); swp(R, 12, 14); swp(R, 13, 15);
    swp(I, 4, 6); swp(I, 5, 7); swp(I, 12, 14); swp(I, 13, 15);
    // C34: packs with bit1=1 flip bit0
    swp(R, 2, 3); swp(R, 6, 7); swp(R, 10, 11); swp(R, 14, 15);
    swp(I, 2, 3); swp(I, 6, 7); swp(I, 10, 11); swp(I, 14, 15);
}

// CNOT(0,1): control = thread bit, target = pack bit3 (predicated SELs).
__device__ __forceinline__ void cnot01(u64* R, u64* I, bool c) {
#pragma unroll
    for (int p = 0; p < 8; p++) {
        u64 a = R[p], b = R[p + 8];
        R[p] = c ? b : a;  R[p + 8] = c ? a : b;
        a = I[p]; b = I[p + 8];
        I[p] = c ? b : a;  I[p + 8] = c ? a : b;
    }
}

__global__ __launch_bounds__(128, 5) void qsim_kernel(
    const float* __restrict__ x, float* __restrict__ out, int Bn)
{
    int gid = blockIdx.x * 128 + threadIdx.x;
    int st = gid >> 1;
    if (st >= Bn) return;
    int t = gid & 1;

    // --- encoding (1 sincos per qubit; double-angle for a/2 terms) ---
    const float4* x4 = reinterpret_cast<const float4*>(x) + (long)st * 6;
    float ur[6][2], ui[6][2];
#pragma unroll
    for (int q = 0; q < 6; q++) {
        float4 v = __ldg(&x4[q]);
        float a = (v.x + v.y + v.z + v.w) * 0.25f;
        a = fminf(6.0f, fmaxf(-6.0f, a)) * (3.14159265358979323846f / 6.0f);
        float s4, c4;
        __sincosf(a * 0.25f, &s4, &c4);
        float s2 = 2.0f * s4 * c4;
        float c2 = fmaf(-2.0f * s4, s4, 1.0f);
        ur[q][0] = c2 * c4;  ui[q][0] = -c2 * s4;
        ur[q][1] = s2 * s4;  ui[q][1] = -s2 * c4;
    }

    // --- build: U0 row t contracted; U1 expands pack bit3 (y1) ---
    float C0r, C0i, C1r, C1i;
    {
        float a0r = g_l1[0], a0i = g_l1[1], b0r = g_l1[2], b0i = g_l1[3];
        C0r = t ? -b0r : a0r;  C0i = t ?  b0i : a0i;
        C1r = t ?  a0r : b0r;  C1i = t ? -a0i : b0i;
    }
    float a1r = g_l1[4], a1i = g_l1[5], b1r = g_l1[6], b1i = g_l1[7];

    float Vr[2][2][2], Vi[2][2][2];  // [y1][y2][y5]
    {
        float Tr[2][2], Ti[2][2];  // [c0][y5]
#pragma unroll
        for (int y5 = 0; y5 < 2; y5++) {
            Tr[0][y5] = C0r * ur[0][y5] - C0i * ui[0][y5];
            Ti[0][y5] = C0r * ui[0][y5] + C0i * ur[0][y5];
            Tr[1][y5] = C1r * ur[0][1 ^ y5] - C1i * ui[0][1 ^ y5];
            Ti[1][y5] = C1r * ui[0][1 ^ y5] + C1i * ur[0][1 ^ y5];
        }
        float Wr[2][2], Wi[2][2];  // [c1][y5]
#pragma unroll
        for (int c1 = 0; c1 < 2; c1++)
#pragma unroll
            for (int y5 = 0; y5 < 2; y5++) {
                int j = c1 ^ y5;
                Wr[c1][y5] = Tr[0][y5] * ur[1][j] - Ti[0][y5] * ui[1][j]
                           + Tr[1][y5] * ur[1][j ^ 1] - Ti[1][y5] * ui[1][j ^ 1];
                Wi[c1][y5] = Tr[0][y5] * ui[1][j] + Ti[0][y5] * ur[1][j]
                           + Tr[1][y5] * ui[1][j ^ 1] + Ti[1][y5] * ur[1][j ^ 1];
            }
        // P[y1][c1][y5] = U1[y1,c1] * W[c1][y5];  U1 = [[a1,b1],[-b1*,a1*]]
        float Pr[2][2][2], Pi2[2][2][2];
#pragma unroll
        for (int y5 = 0; y5 < 2; y5++) {
            Pr[0][0][y5]  = a1r * Wr[0][y5] - a1i * Wi[0][y5];
            Pi2[0][0][y5] = a1r * Wi[0][y5] + a1i * Wr[0][y5];
            Pr[0][1][y5]  = b1r * Wr[1][y5] - b1i * Wi[1][y5];
            Pi2[0][1][y5] = b1r * Wi[1][y5] + b1i * Wr[1][y5];
            Pr[1][0][y5]  = -b1r * Wr[0][y5] - b1i * Wi[0][y5];
            Pi2[1][0][y5] = -b1r * Wi[0][y5] + b1i * Wr[0][y5];
            Pr[1][1][y5]  = a1r * Wr[1][y5] + a1i * Wi[1][y5];
            Pi2[1][1][y5] = a1r * Wi[1][y5] - a1i * Wr[1][y5];
        }
#pragma unroll
        for (int y1 = 0; y1 < 2; y1++)
#pragma unroll
            for (int y2 = 0; y2 < 2; y2++)
#pragma unroll
                for (int y5 = 0; y5 < 2; y5++) {
                    Vr[y1][y2][y5] =
                        Pr[y1][0][y5] * ur[2][y2] - Pi2[y1][0][y5] * ui[2][y2]
                      + Pr[y1][1][y5] * ur[2][y2 ^ 1] - Pi2[y1][1][y5] * ui[2][y2 ^ 1];
                    Vi[y1][y2][y5] =
                        Pr[y1][0][y5] * ui[2][y2] + Pi2[y1][0][y5] * ur[2][y2]
                      + Pr[y1][1][y5] * ui[2][y2 ^ 1] + Pi2[y1][1][y5] * ur[2][y2 ^ 1];
                }
    }
    // pack over lane y5, expand y3 via u3[y2^y3]
    u64 CRm[2][2][2], CIm[2][2][2];  // [y1][y2][y3]
    {
        u64 w3r[2], w3i[2], n3i[2];
        w3r[0] = bc2(ur[3][0]); w3i[0] = bc2(ui[3][0]); n3i[0] = w3i[0] ^ SGN2;
        w3r[1] = bc2(ur[3][1]); w3i[1] = bc2(ui[3][1]); n3i[1] = w3i[1] ^ SGN2;
#pragma unroll
        for (int y1 = 0; y1 < 2; y1++)
#pragma unroll
            for (int y2 = 0; y2 < 2; y2++) {
                u64 BR = pk2(Vr[y1][y2][0], Vr[y1][y2][1]);
                u64 BI = pk2(Vi[y1][y2][0], Vi[y1][y2][1]);
#pragma unroll
                for (int y3 = 0; y3 < 2; y3++) {
                    int m = y2 ^ y3;
                    CRm[y1][y2][y3] = f2fma(n3i[m], BI, f2mul(w3r[m], BR));
                    CIm[y1][y2][y3] = f2fma(w3i[m], BR, f2mul(w3r[m], BI));
                }
            }
    }
    // K[y3][y4] (lane-packed) = u4[y4^y3]*u5[y4^y5]; expand y4 (bit0)
    u64 R[16], I[16];
    {
        float k45r[2][2], k45i[2][2];
#pragma unroll
        for (int m = 0; m < 2; m++)
#pragma unroll
            for (int n = 0; n < 2; n++) {
                k45r[m][n] = ur[4][m] * ur[5][n] - ui[4][m] * ui[5][n];
                k45i[m][n] = ur[4][m] * ui[5][n] + ui[4][m] * ur[5][n];
            }
        u64 KR[2][2], KI[2][2];
#pragma unroll
        for (int y3 = 0; y3 < 2; y3++)
#pragma unroll
            for (int y4 = 0; y4 < 2; y4++) {
                int m = y4 ^ y3;
                KR[y3][y4] = pk2(k45r[m][y4], k45r[m][y4 ^ 1]);
                KI[y3][y4] = pk2(k45i[m][y4], k45i[m][y4 ^ 1]);
            }
#pragma unroll
        for (int p = 0; p < 16; p++) {
            int y1 = (p >> 3) & 1, y2 = (p >> 2) & 1, y3 = (p >> 1) & 1, y4 = p & 1;
            R[p] = f2fma(KI[y3][y4] ^ SGN2, CIm[y1][y2][y3],
                         f2mul(KR[y3][y4], CRm[y1][y2][y3]));
            I[p] = f2fma(KI[y3][y4], CRm[y1][y2][y3],
                         f2mul(KR[y3][y4], CIm[y1][y2][y3]));
        }
    }

    // --- layer-1 local gates (q2,q3,q4,q5) ---
    su2_loc<4>(R, I, g_u + 16);
    su2_loc<2>(R, I, g_u + 24);
    su2_loc<1>(R, I, g_u + 32);
    su2_q5(R, I, g_u + 40);

    // --- layer 2 (full) ---
    {
        const u64* cf = g_u + 48;
        cnot01(R, I, t != 0);
        cnot_ring_mid(R, I);

        // q0 gate (cross-thread, partner xor 1), C45 + C50 folded into gather.
        {
            u64 smask = t ? SGN2 : 0ULL;
            u64 car  = cf[0];
            u64 cai  = cf[1] ^ smask;
            u64 ncai = cai ^ SGN2;
            u64 cbr  = cf[2] ^ smask;
            u64 cbi  = cf[3];
            u64 ncbi = cf[4];
#pragma unroll
            for (int p = 0; p < 16; p++) {
                u64 LR = R[p], LI = I[p];
                u64 MR = __shfl_xor_sync(0xffffffffu, LR, 1);
                u64 MI = __shfl_xor_sync(0xffffffffu, LI, 1);
                float lr0, lr1, li0, li1, mr0, mr1, mi0, mi1;
                upk2(LR, lr0, lr1); upk2(LI, li0, li1);
                upk2(MR, mr0, mr1); upk2(MI, mi0, mi1);
                u64 AR, AI, BR, BI;
                if ((p & 1) == 0) {  // q4=0: C45 identity, C50 hi-lane cross
                    AR = pk2(lr0, mr1); AI = pk2(li0, mi1);
                    BR = pk2(mr0, lr1); BI = pk2(mi0, li1);
                } else {             // q4=1: C45 lane-swap then C50
                    AR = pk2(lr1, mr0); AI = pk2(li1, mi0);
                    BR = pk2(mr1, lr0); BI = pk2(mi1, li0);
                }
                R[p] = f2fma(ncbi, BI, f2fma(cbr, BR, f2fma(ncai, AI, f2mul(car, AR))));
                I[p] = f2fma(cbi, BR, f2fma(cbr, BI, f2fma(cai, AR, f2mul(car, AI))));
            }
        }

        su2_loc<8>(R, I, cf + 8);   // q1 (bit3)
        su2_loc<4>(R, I, cf + 16);  // q2 (bit2)
        su2_loc<2>(R, I, cf + 24);  // q3 (bit1)
        su2_loc<1>(R, I, cf + 32);  // q4 (bit0)
        su2_q5(R, I, cf + 40);      // q5 (lane)
    }

    // --- layer-3 prefix: C01 SEL + C12/C23/C34 renames; rest absorbed ---
    cnot01(R, I, t != 0);
    cnot_ring_mid(R, I);

    // --- measurements, phase 1: local (pr-based + pack-local cross) ---
    float sZ1, sZ2, sZ3, sZ4, sZ45;
    float sEx1, sEy1, sEx2, sEy2, sEx3, sEy3, sX45, sY45;
    {
        u64 az1 = 0, az2 = 0, az3 = 0, az4 = 0;
        u64 ex1 = 0, ey1 = 0, ex2 = 0, ey2 = 0, ex3 = 0, ey3 = 0;
        u64 x45 = 0, y45 = 0;
#pragma unroll
        for (int p = 0; p < 16; p++) {
            u64 pr = f2fma(I[p], I[p], f2mul(R[p], R[p]));
            az1 = f2add(az1, (p & 8) ? (pr ^ SGN2) : pr);
            az2 = f2add(az2, (p & 4) ? (pr ^ SGN2) : pr);
            az3 = f2add(az3, (p & 2) ? (pr ^ SGN2) : pr);
            az4 = f2add(az4, (p & 1) ? (pr ^ SGN2) : pr);
            if (!(p & 8)) {
                ex1 = f2fma(R[p], R[p | 8], f2fma(I[p], I[p | 8], ex1));
                ey1 = f2fma(R[p], I[p | 8], f2fma(I[p] ^ SGN2, R[p | 8], ey1));
            }
            if (!(p & 4)) {
                ex2 = f2fma(R[p], R[p | 4], f2fma(I[p], I[p | 4], ex2));
                ey2 = f2fma(R[p], I[p | 4], f2fma(I[p] ^ SGN2, R[p | 4], ey2));
            }
            if (!(p & 2)) {
                ex3 = f2fma(R[p], R[p | 2], f2fma(I[p], I[p | 2], ex3));
                ey3 = f2fma(R[p], I[p | 2], f2fma(I[p] ^ SGN2, R[p | 2], ey3));
            }
            x45 = f2fma(R[p], f2swap(R[p ^ 1]), f2fma(I[p], f2swap(I[p ^ 1]), x45));
            if (!(p & 1)) {
                y45 = f2fma(R[p], f2swap(I[p | 1]),
                            f2fma(I[p] ^ SGN2, f2swap(R[p | 1]), y45));
            }
        }
        float lo, hi;
        upk2(az1, lo, hi); sZ1  = lo + hi;
        upk2(az2, lo, hi); sZ2  = lo + hi;
        upk2(az3, lo, hi); sZ3  = lo + hi;
        upk2(az4, lo, hi); sZ4  = lo + hi; sZ45 = lo - hi;
        upk2(ex1, lo, hi); sEx1 = lo + hi;
        upk2(ey1, lo, hi); sEy1 = lo + hi;
        upk2(ex2, lo, hi); sEx2 = lo + hi;
        upk2(ey2, lo, hi); sEy2 = lo + hi;
        upk2(ex3, lo, hi); sEx3 = lo + hi;
        upk2(ey3, lo, hi); sEy3 = lo + hi;
        upk2(x45, lo, hi); sX45 = lo + hi;
        upk2(y45, lo, hi); sY45 = lo + hi;
    }

    // --- phase 2: cross-thread q0 observables (partner = lane xor 1) ---
    float sX0, sZY0, sX50, sZYX;
    {
        u64 ax0 = 0, zy0 = 0, x50 = 0, zyx = 0;
#pragma unroll
        for (int p = 0; p < 16; p++) {
            u64 PR = __shfl_xor_sync(0xffffffffu, R[p], 1);
            u64 PI = __shfl_xor_sync(0xffffffffu, I[p], 1);
            ax0 = f2fma(R[p], PR, f2fma(I[p], PI, ax0));
            {
                u64 v = f2fma(R[p], PI, f2mul(I[p] ^ SGN2, PR));
                zy0 = f2add(zy0, (p & 1) ? (v ^ SGN2) : v);
            }
            x50 = f2fma(R[p], f2swap(PR), f2fma(I[p], f2swap(PI), x50));
            {
                u64 v = f2fma(R[p], f2swap(PI), f2mul(I[p] ^ SGN2, f2swap(PR)));
                zyx = f2add(zyx, (p & 1) ? (v ^ SGN2) : v);
            }
        }
        float lo, hi;
        upk2(ax0, lo, hi); sX0  = lo + hi;
        upk2(zy0, lo, hi); sZY0 = lo - hi;
        upk2(x50, lo, hi); sX50 = lo + hi;
        upk2(zyx, lo, hi); sZYX = lo - hi;
    }

    float sgT = t ? -1.0f : 1.0f;  // q0 role sign (q0 = thread bit)

    float m0 = g_m[2]  * (sgT * sZ45) + g_m[0]  * sX0  + g_m[1]  * (sgT * sZY0);
    float m1 = g_m[6]  * sZ1          + g_m[4]  * sEx1 + g_m[5]  * sEy1;
    float m2 = g_m[10] * sZ2          + g_m[8]  * sEx2 + g_m[9]  * sEy2;
    float m3 = g_m[14] * sZ3          + g_m[12] * sEx3 + g_m[13] * sEy3;
    float m4 = g_m[18] * sZ4          + g_m[16] * sX45 + g_m[17] * sY45;
    float m5 = g_m[22] * sZ45         + g_m[20] * sX50 + g_m[21] * sZYX;

    // reduce across the 2-thread group
    m0 += __shfl_xor_sync(0xffffffffu, m0, 1);
    m1 += __shfl_xor_sync(0xffffffffu, m1, 1);
    m2 += __shfl_xor_sync(0xffffffffu, m2, 1);
    m3 += __shfl_xor_sync(0xffffffffu, m3, 1);
    m4 += __shfl_xor_sync(0xffffffffu, m4, 1);
    m5 += __shfl_xor_sync(0xffffffffu, m5, 1);

    if (t == 0) {
        float4* o4 = reinterpret_cast<float4*>(out) + (long)st * 2;
        o4[0] = make_float4(m0, m1, m2, m3);
        o4[1] = make_float4(m4, m5, m0, m1);
    }
}

extern "C" void kernel_launch(void* const* d_in, const int* in_sizes, int n_in,
                              void* d_out, int out_size) {
    const float* x     = (const float*)d_in[0];
    const float* theta = (const float*)d_in[1];
    float* out = (float*)d_out;
    int Bn = in_sizes[0] / 24;

    prep_kernel<<<1, 32>>>(theta);
    long threads = 2L * Bn;
    int blocks = (int)((threads + 127) / 128);
    qsim_kernel<<<blocks, 128>>>(x, out, Bn);
}